// round 5
// baseline (speedup 1.0000x reference)
#include <cuda_runtime.h>
#include <cuda_bf16.h>
#include <math.h>

// Problem constants (fixed-shape problem)
#define BB 4
#define HH_ 180
#define WW 180
#define SPATIAL (HH_ * WW)       // 32400
#define C_L 128
#define C_C 128
#define CH_ALL 512
#define CH_HID 170
#define C_OUT 256

typedef unsigned int u32;
typedef unsigned long long u64;

// ---- fused kernel smem map (bytes) ----
// A/h hi: [128m][256k] bf16, 512B rows, xor-swizzled : 0      .. 65535
// A/h lo:                                             : 65536  .. 131071
// B buf0/buf1: [256n][32k hi | 32k lo] 128B rows      : 131072 .. 196607
#define SM_AH 0
#define SM_AL 65536
#define SM_B  131072
#define SMEM_TOTAL 196608

// ---------------- device scratch ----------------------------------------------
__device__ __align__(16) float g_imgT[SPATIAL * C_C];     // img batch0 [pixel][chan]
__device__ unsigned g_keys[BB * CH_ALL];
__device__ __align__(16) float g_hid[2][BB][CH_HID];
__device__ __align__(16) float g_att_l[BB * C_L];
__device__ __align__(16) float g_att_c[BB * C_C];
// pre-swizzled weight images: 8 panels x 32KB (rows: [n][32k hi | 32k lo])
__device__ __align__(16) __nv_bfloat16 g_B1[131072];      // 256KB
__device__ __align__(16) __nv_bfloat16 g_B2[131072];

// ---------------- helpers -------------------------------------------------------
__device__ __forceinline__ u32 smem_u32(const void* p) {
    u32 r;
    asm("{ .reg .u64 t; cvta.to.shared.u64 t, %1; cvt.u32.u64 %0, t; }" : "=r"(r) : "l"(p));
    return r;
}
__device__ __forceinline__ void cp16(u32 dst, const void* src) {
    asm volatile("cp.async.cg.shared.global [%0], [%1], 16;" :: "r"(dst), "l"(src) : "memory");
}
__device__ __forceinline__ void cp_commit() { asm volatile("cp.async.commit_group;" ::: "memory"); }
__device__ __forceinline__ void cp_wait0()  { asm volatile("cp.async.wait_group 0;" ::: "memory"); }
__device__ __forceinline__ void cp_wait1()  { asm volatile("cp.async.wait_group 1;" ::: "memory"); }

__device__ __forceinline__ void ldsm4(u32 a, u32 &r0, u32 &r1, u32 &r2, u32 &r3) {
    asm volatile("ldmatrix.sync.aligned.m8n8.x4.shared.b16 {%0,%1,%2,%3}, [%4];"
                 : "=r"(r0), "=r"(r1), "=r"(r2), "=r"(r3) : "r"(a));
}
__device__ __forceinline__ void mma16816(float* c, const u32* a, u32 b0, u32 b1) {
    asm volatile("mma.sync.aligned.m16n8k16.row.col.f32.bf16.bf16.f32 "
                 "{%0,%1,%2,%3}, {%4,%5,%6,%7}, {%8,%9}, {%0,%1,%2,%3};"
                 : "+f"(c[0]), "+f"(c[1]), "+f"(c[2]), "+f"(c[3])
                 : "r"(a[0]), "r"(a[1]), "r"(a[2]), "r"(a[3]), "r"(b0), "r"(b1));
}

// pack two fp32 -> bf16x2 word (low16 = v0, high16 = v1), rn
__device__ __forceinline__ u32 pk_bf16(float v0, float v1) {
    u32 r; asm("cvt.rn.bf16x2.f32 %0, %1, %2;" : "=r"(r) : "f"(v1), "f"(v0)); return r;
}
// hi/lo split of a fp32 pair into two bf16x2 words
__device__ __forceinline__ void split2(float v0, float v1, u32 &h, u32 &l) {
    h = pk_bf16(v0, v1);
    float h0 = __uint_as_float(h << 16);
    float h1 = __uint_as_float(h & 0xFFFF0000u);
    l = pk_bf16(v0 - h0, v1 - h1);
}

// Order-preserving float <-> uint encoding for atomic min/max
__device__ __forceinline__ unsigned enc_f(float x) {
    unsigned u = __float_as_uint(x);
    return (u & 0x80000000u) ? ~u : (u | 0x80000000u);
}
__device__ __forceinline__ float dec_f(unsigned k) {
    unsigned u = (k & 0x80000000u) ? (k ^ 0x80000000u) : ~k;
    return __uint_as_float(u);
}

// ---------------- kernel 0: init min/max keys -----------------------------------
__global__ void init_keys_kernel() {
    int i = blockIdx.x * blockDim.x + threadIdx.x;
    if (i >= BB * CH_ALL) return;
    int slot = i & (CH_ALL - 1);
    bool is_min = (slot < 128) || (slot >= 256 && slot < 384);
    g_keys[i] = is_min ? 0xFFFFFFFFu : 0x00000000u;
}

// ---------------- kernel 1: transpose img_bev[0] [C][P] -> [P][C] ---------------
__global__ void transpose_kernel(const float* __restrict__ img) {
    __shared__ float tile[32][33];
    int p0 = blockIdx.x * 32;
    int c0 = blockIdx.y * 32;
    int tx = threadIdx.x, ty = threadIdx.y;
#pragma unroll
    for (int j = 0; j < 4; ++j) {
        int c = c0 + ty + j * 8;
        int p = p0 + tx;
        if (p < SPATIAL) tile[ty + j * 8][tx] = img[c * SPATIAL + p];
    }
    __syncthreads();
#pragma unroll
    for (int j = 0; j < 4; ++j) {
        int p = p0 + ty + j * 8;
        int c = c0 + tx;
        if (p < SPATIAL) g_imgT[p * C_C + c] = tile[tx][ty + j * 8];
    }
}

// ---------------- kernel 2: per-batch segment min/max ---------------------------
// 1024-row chunks; batch-uniform fast path with 8 independent min/max chains.
#define MM_CHUNK 1024
__device__ __forceinline__ void flush_mm(int b, int c, float mn, float mx) {
    int msl, xsl;
    if (c < 128) { msl = c;             xsl = 128 + c; }
    else         { msl = 256 + c - 128; xsl = 384 + c - 128; }
    atomicMin(&g_keys[b * CH_ALL + msl], enc_f(mn));
    atomicMax(&g_keys[b * CH_ALL + xsl], enc_f(mx));
}
__global__ void __launch_bounds__(256) minmax_kernel(
    const float* __restrict__ lidar, const int* __restrict__ batch_idx,
    const int* __restrict__ y_idx, const int* __restrict__ x_idx, int N)
{
    __shared__ int sb[MM_CHUNK];
    __shared__ int sr[MM_CHUNK];
    int tid = threadIdx.x;
    int n0 = blockIdx.x * MM_CHUNK;
    int cnt = N - n0; if (cnt > MM_CHUNK) cnt = MM_CHUNK;
    if (cnt <= 0) return;
    for (int i = tid; i < cnt; i += 256) {
        int n = n0 + i;
        int b = batch_idx[n];
        int r = b * SPATIAL + y_idx[n] * WW + x_idx[n];
        if (r > SPATIAL - 2) r = SPATIAL - 2;
        sb[i] = b; sr[i] = r;
    }
    __syncthreads();
    const int c = tid;
    const bool cam = (c >= 128);
    const float* base = cam ? (g_imgT + (c - 128)) : (lidar + c);

    if (sb[0] == sb[cnt - 1]) {
        // uniform chunk: 8 independent chains for memory-level parallelism
        float mn[8], mx[8];
#pragma unroll
        for (int q = 0; q < 8; ++q) { mn[q] = INFINITY; mx[q] = -INFINITY; }
        int i = 0;
        for (; i + 8 <= cnt; i += 8) {
            float v[8];
#pragma unroll
            for (int q = 0; q < 8; ++q)
                v[q] = cam ? base[(size_t)sr[i + q] * C_C]
                           : base[(size_t)(n0 + i + q) * C_L];
#pragma unroll
            for (int q = 0; q < 8; ++q) {
                mn[q] = fminf(mn[q], v[q]);
                mx[q] = fmaxf(mx[q], v[q]);
            }
        }
        for (; i < cnt; ++i) {
            float v = cam ? base[(size_t)sr[i] * C_C] : base[(size_t)(n0 + i) * C_L];
            mn[0] = fminf(mn[0], v); mx[0] = fmaxf(mx[0], v);
        }
#pragma unroll
        for (int q = 1; q < 8; ++q) {
            mn[0] = fminf(mn[0], mn[q]);
            mx[0] = fmaxf(mx[0], mx[q]);
        }
        flush_mm(sb[0], c, mn[0], mx[0]);
    } else {
        // rare chunk containing a batch boundary: scalar path with flushes
        float mn = INFINITY, mx = -INFINITY;
        int cur = sb[0];
        for (int i = 0; i < cnt; ++i) {
            int b = sb[i];
            if (b != cur) { flush_mm(cur, c, mn, mx); cur = b; mn = INFINITY; mx = -INFINITY; }
            float v = cam ? base[(size_t)sr[i] * C_C] : base[(size_t)(n0 + i) * C_L];
            mn = fminf(mn, v); mx = fmaxf(mx, v);
        }
        flush_mm(cur, c, mn, mx);
    }
}

// ---------------- kernel 3a/3b: tiny gating MLPs --------------------------------
__global__ void __launch_bounds__(256) mlp1_kernel(
    const float* __restrict__ Wl1, const float* __restrict__ Wc1)
{
    int gw   = blockIdx.x * 8 + (threadIdx.x >> 5);
    int lane = threadIdx.x & 31;
    int net  = gw / (BB * CH_HID);
    int rem  = gw % (BB * CH_HID);
    int b    = rem / CH_HID;
    int j    = rem % CH_HID;
    const float* W = net ? Wc1 : Wl1;
    float s = 0.f;
#pragma unroll
    for (int t = 0; t < 16; ++t) {
        int k = lane + 32 * t;
        s = fmaf(dec_f(g_keys[b * CH_ALL + k]), W[k * CH_HID + j], s);
    }
#pragma unroll
    for (int o = 16; o; o >>= 1) s += __shfl_xor_sync(0xffffffffu, s, o);
    if (lane == 0) g_hid[net][b][j] = fmaxf(s, 0.f);
}
__global__ void __launch_bounds__(256) mlp2_kernel(
    const float* __restrict__ Wl2, const float* __restrict__ Wc2)
{
    int idx = blockIdx.x * 256 + threadIdx.x;
    int net = idx >> 9, rem = idx & 511;
    int b = rem >> 7, cc = rem & 127;
    const float* W2 = net ? Wc2 : Wl2;
    const float* h  = g_hid[net][b];
    float s = 0.f;
    for (int k = 0; k < CH_HID; ++k) s = fmaf(h[k], W2[k * 128 + cc], s);
    float v = fmaxf(s, 0.f);
    (net ? g_att_c : g_att_l)[b * 128 + cc] = 1.f / (1.f + expf(-v));
}

// ---------------- kernel 3c: weight prep (transpose + split + pre-swizzle) ------
__global__ void __launch_bounds__(256) weight_prep_kernel(
    const float* __restrict__ Wf1, const float* __restrict__ Wf2)
{
    int idx = blockIdx.x * 256 + threadIdx.x;   // 2 * 65536
    int mat = idx >> 16;
    int rem = idx & 65535;
    int k = rem >> 8;          // 0..255 input dim
    int n = rem & 255;         // 0..255 output dim
    const float* W = mat ? Wf2 : Wf1;
    float v = W[k * 256 + n];
    u32 hh = pk_bf16(v, 0.f);
    float hf = __uint_as_float(hh << 16);
    u32 ll = pk_bf16(v - hf, 0.f);
    int p = k >> 5, kl = k & 31, k8l = kl >> 3, e = k & 7;
    u32 base = (u32)p * 32768u + (u32)n * 128u + (u32)e * 2u;
    u32 offh = base + ((u32)(k8l ^ (n & 7)) << 4);
    u32 offl = base + ((u32)((k8l + 4) ^ (n & 7)) << 4);
    __nv_bfloat16* img = mat ? g_B2 : g_B1;
    *(unsigned short*)((char*)img + offh) = (unsigned short)(hh & 0xFFFFu);
    *(unsigned short*)((char*)img + offl) = (unsigned short)(ll & 0xFFFFu);
}

// ---------------- fused GEMM stage (M=128) -----------------------------------------
// acc += A(smem hi/lo, 128x256 bf16) x B(img), K=256 in 8 panels of 32,
// cp.async double-buffered.  Warp tile 64m x 64n (8 warps: 2m x 4n).
__device__ __forceinline__ void gemm_stage(
    u32 smb, const uint4* __restrict__ Bimg,
    float acc[4][8][4], int tid, int lane, int wm, int wn)
{
    const u32 Bb = smb + SM_B;
    const u32 Ah = smb + SM_AH;
    // preload panel 0 -> buf0
    {
        u32 dst = Bb + (u32)tid * 16u;
        const uint4* s = Bimg + tid;
#pragma unroll
        for (int i = 0; i < 8; ++i) cp16(dst + i * 4096u, s + i * 256);
        cp_commit();
    }
#pragma unroll 1
    for (int p = 0; p < 8; ++p) {
        if (p < 7) {
            u32 dst = Bb + (u32)((p + 1) & 1) * 32768u + (u32)tid * 16u;
            const uint4* s = Bimg + (p + 1) * 2048 + tid;
#pragma unroll
            for (int i = 0; i < 8; ++i) cp16(dst + i * 4096u, s + i * 256);
            cp_commit();
            cp_wait1();
        } else {
            cp_wait0();
        }
        __syncthreads();
        u32 B = Bb + (u32)(p & 1) * 32768u;
#pragma unroll
        for (int s = 0; s < 2; ++s) {
            int k8 = p * 4 + s * 2 + (lane >> 4);
            // ---- A hi fragments: 4 m16 tiles ----
            u32 ah[4][4];
#pragma unroll
            for (int t = 0; t < 4; ++t) {
                int arow = wm + t * 16 + (lane & 15);
                u32 aoff = (u32)arow * 512u + ((u32)(k8 ^ (arow & 7)) << 4);
                ldsm4(Ah + aoff, ah[t][0], ah[t][1], ah[t][2], ah[t][3]);
            }
            // ---- B hi fragments: 8 n8 ----
            int k8h = s * 2 + (lane >> 4);
            u32 bh[8][2];
#pragma unroll
            for (int j16 = 0; j16 < 4; ++j16) {
                int brow = wn + j16 * 16 + (lane & 15);
                u32 rb = B + (u32)brow * 128u;
                u32 r0, r1, r2, r3;
                ldsm4(rb + ((u32)(k8h ^ (brow & 7)) << 4), r0, r1, r2, r3);
                bh[2*j16][0] = r0;   bh[2*j16][1] = r2;
                bh[2*j16+1][0] = r1; bh[2*j16+1][1] = r3;
            }
            // term 1: Ah x Bh
#pragma unroll
            for (int t = 0; t < 4; ++t)
#pragma unroll
                for (int j = 0; j < 8; ++j)
                    mma16816(acc[t][j], ah[t], bh[j][0], bh[j][1]);
            // ---- A lo fragments ----
            u32 al[4][4];
#pragma unroll
            for (int t = 0; t < 4; ++t) {
                int arow = wm + t * 16 + (lane & 15);
                u32 aoff = (u32)arow * 512u + ((u32)(k8 ^ (arow & 7)) << 4);
                ldsm4(Ah + 65536u + aoff, al[t][0], al[t][1], al[t][2], al[t][3]);
            }
            // term 2: Al x Bh
#pragma unroll
            for (int t = 0; t < 4; ++t)
#pragma unroll
                for (int j = 0; j < 8; ++j)
                    mma16816(acc[t][j], al[t], bh[j][0], bh[j][1]);
            // ---- B lo fragments ----
            u32 bl[8][2];
#pragma unroll
            for (int j16 = 0; j16 < 4; ++j16) {
                int brow = wn + j16 * 16 + (lane & 15);
                u32 rb = B + (u32)brow * 128u;
                u32 r0, r1, r2, r3;
                ldsm4(rb + ((u32)((k8h + 4) ^ (brow & 7)) << 4), r0, r1, r2, r3);
                bl[2*j16][0] = r0;   bl[2*j16][1] = r2;
                bl[2*j16+1][0] = r1; bl[2*j16+1][1] = r3;
            }
            // term 3: Ah x Bl
#pragma unroll
            for (int t = 0; t < 4; ++t)
#pragma unroll
                for (int j = 0; j < 8; ++j)
                    mma16816(acc[t][j], ah[t], bl[j][0], bl[j][1]);
        }
        __syncthreads();
    }
}

// ---------------- kernel 4: fused gate + GEMM1 + ReLU + GEMM2 + ReLU -------------
__global__ void __launch_bounds__(256, 1) fused_mma_kernel(
    const float* __restrict__ lidar,
    const int* __restrict__ batch_idx,
    const int* __restrict__ y_idx,
    const int* __restrict__ x_idx,
    float* __restrict__ out, int N)
{
    extern __shared__ char sm[];
    const u32 smb = smem_u32(sm);
    const int tid  = threadIdx.x;
    const int lane = tid & 31;
    const int wid  = tid >> 5;
    const int wm   = (wid & 1) * 64;
    const int wn   = (wid >> 1) * 64;

    // ---- phase 1: gather + gate + bf16 split into A smem (swizzled) ----
    {
        int m = tid >> 1, half = tid & 1;
        int n = blockIdx.x * 128 + m;
        int nn = n < N ? n : N - 1;
        int b = batch_idx[nn];
        const float* src;
        const float* att;
        if (half) {
            int r = b * SPATIAL + y_idx[nn] * WW + x_idx[nn];
            if (r > SPATIAL - 2) r = SPATIAL - 2;
            src = g_imgT + (size_t)r * C_C; att = g_att_c + b * 128;
        } else {
            src = lidar + (size_t)nn * C_L; att = g_att_l + b * 128;
        }
        const float4* s4 = (const float4*)src;
        const float4* g4 = (const float4*)att;
        u32 rowb = (u32)m * 512u;
        u32 xm = (u32)(m & 7);
#pragma unroll
        for (int i = 0; i < 16; ++i) {
            float4 a0 = s4[2*i], a1 = s4[2*i + 1];
            float4 q0 = g4[2*i], q1 = g4[2*i + 1];
            float v0 = a0.x*q0.x, v1 = a0.y*q0.y, v2 = a0.z*q0.z, v3 = a0.w*q0.w;
            float v4 = a1.x*q1.x, v5 = a1.y*q1.y, v6 = a1.z*q1.z, v7 = a1.w*q1.w;
            uint4 H, L;
            split2(v0, v1, H.x, L.x); split2(v2, v3, H.y, L.y);
            split2(v4, v5, H.z, L.z); split2(v6, v7, H.w, L.w);
            u32 k8 = (u32)(half * 16 + i);      // 0..31
            u32 off = rowb + ((k8 ^ xm) << 4);
            *(uint4*)(sm + SM_AH + off) = H;
            *(uint4*)(sm + SM_AL + off) = L;
        }
    }
    // (first __syncthreads inside gemm_stage covers A writes)

    float acc[4][8][4];
#pragma unroll
    for (int t = 0; t < 4; ++t)
#pragma unroll
        for (int j = 0; j < 8; ++j)
#pragma unroll
            for (int c = 0; c < 4; ++c) acc[t][j][c] = 0.f;

    // ---- GEMM1 ----
    gemm_stage(smb, (const uint4*)g_B1, acc, tid, lane, wm, wn);

    // ---- epilogue 1: relu + split -> h (reuses A smem region) ----
    {
#pragma unroll
        for (int t = 0; t < 4; ++t) {
            int r0 = wm + 16 * t + (lane >> 2);
            int r1 = r0 + 8;
#pragma unroll
            for (int j = 0; j < 8; ++j) {
                float* c = acc[t][j];
                u32 k8 = (u32)((wn >> 3) + j);
                u32 eb = (u32)(lane & 3) * 4u;
                float v0 = fmaxf(c[0], 0.f), v1 = fmaxf(c[1], 0.f);
                float v2 = fmaxf(c[2], 0.f), v3 = fmaxf(c[3], 0.f);
                u32 h0, l0, h1, l1;
                split2(v0, v1, h0, l0);
                split2(v2, v3, h1, l1);
                u32 o0 = (u32)r0 * 512u + ((k8 ^ (u32)(r0 & 7)) << 4) + eb;
                u32 o1 = (u32)r1 * 512u + ((k8 ^ (u32)(r1 & 7)) << 4) + eb;
                *(u32*)(sm + SM_AH + o0) = h0;
                *(u32*)(sm + SM_AL + o0) = l0;
                *(u32*)(sm + SM_AH + o1) = h1;
                *(u32*)(sm + SM_AL + o1) = l1;
            }
        }
    }
    __syncthreads();

#pragma unroll
    for (int t = 0; t < 4; ++t)
#pragma unroll
        for (int j = 0; j < 8; ++j)
#pragma unroll
            for (int c = 0; c < 4; ++c) acc[t][j][c] = 0.f;

    // ---- GEMM2 ----
    gemm_stage(smb, (const uint4*)g_B2, acc, tid, lane, wm, wn);

    // ---- epilogue 2: relu -> gmem ----
    {
        int mbase = blockIdx.x * 128;
#pragma unroll
        for (int t = 0; t < 4; ++t) {
            int r0 = mbase + wm + 16 * t + (lane >> 2);
            int r1 = r0 + 8;
#pragma unroll
            for (int j = 0; j < 8; ++j) {
                float* c = acc[t][j];
                int col = wn + 8 * j + 2 * (lane & 3);
                if (r0 < N) {
                    float2 v = make_float2(fmaxf(c[0], 0.f), fmaxf(c[1], 0.f));
                    *(float2*)(out + (size_t)r0 * 256 + col) = v;
                }
                if (r1 < N) {
                    float2 v = make_float2(fmaxf(c[2], 0.f), fmaxf(c[3], 0.f));
                    *(float2*)(out + (size_t)r1 * 256 + col) = v;
                }
            }
        }
    }
}

// ---------------- host launcher ---------------------------------------------------
extern "C" void kernel_launch(void* const* d_in, const int* in_sizes, int n_in,
                              void* d_out, int out_size)
{
    int iL = -1, iImg = -1, iB = -1, iY = -1, iX = -1;
    int iWl1 = -1, iWl2 = -1, iWc1 = -1, iWc2 = -1, iWf1 = -1, iWf2 = -1;
    for (int i = 0; i < n_in; ++i) {
        int s = in_sizes[i];
        if      (s == BB * C_C * SPATIAL)      iImg = i;
        else if (s == CH_ALL * CH_HID)         { if (iWl1 < 0) iWl1 = i; else iWc1 = i; }
        else if (s == CH_HID * C_L)            { if (iWl2 < 0) iWl2 = i; else iWc2 = i; }
        else if (s == C_OUT * C_OUT)           { if (iWf1 < 0) iWf1 = i; else iWf2 = i; }
        else if (s % C_L == 0 && s >= 1000000) iL = i;
        else                                   { if (iB < 0) iB = i; else if (iY < 0) iY = i; else iX = i; }
    }
    const float* lidar = (const float*)d_in[iL];
    const float* img   = (const float*)d_in[iImg];
    const int*   bidx  = (const int*)d_in[iB];
    const int*   yidx  = (const int*)d_in[iY];
    const int*   xidx  = (const int*)d_in[iX];
    const float* Wl1   = (const float*)d_in[iWl1];
    const float* Wl2   = (const float*)d_in[iWl2];
    const float* Wc1   = (const float*)d_in[iWc1];
    const float* Wc2   = (const float*)d_in[iWc2];
    const float* Wf1   = (const float*)d_in[iWf1];
    const float* Wf2   = (const float*)d_in[iWf2];
    float* out = (float*)d_out;
    const int N = in_sizes[iL] / C_L;

    cudaFuncSetAttribute(fused_mma_kernel, cudaFuncAttributeMaxDynamicSharedMemorySize, SMEM_TOTAL);

    init_keys_kernel<<<(BB * CH_ALL + 255) / 256, 256>>>();
    transpose_kernel<<<dim3((SPATIAL + 31) / 32, C_C / 32), dim3(32, 8)>>>(img);
    weight_prep_kernel<<<512, 256>>>(Wf1, Wf2);
    minmax_kernel<<<(N + MM_CHUNK - 1) / MM_CHUNK, 256>>>(lidar, bidx, yidx, xidx, N);
    mlp1_kernel<<<CH_HID, 256>>>(Wl1, Wc1);
    mlp2_kernel<<<4, 256>>>(Wl2, Wc2);
    fused_mma_kernel<<<(N + 127) / 128, 256, SMEM_TOTAL>>>(lidar, bidx, yidx, xidx, out, N);
    (void)out_size;
}

// round 6
// speedup vs baseline: 2.3043x; 2.3043x over previous
#include <cuda_runtime.h>
#include <cuda_fp16.h>
#include <math.h>

// Problem constants (fixed-shape problem)
#define BB 4
#define HH_ 180
#define WW 180
#define SPATIAL (HH_ * WW)       // 32400
#define C_L 128
#define C_C 128
#define CH_ALL 512
#define CH_HID 170
#define C_OUT 256

typedef unsigned int u32;
typedef unsigned long long u64;

// ---- fused kernel smem map (bytes) ----
// A hi: [64m][256k] fp16, 512B rows, xor-swizzled : 0      .. 32767
// A lo:                                            : 32768  .. 65535
// h hi: same layout                                : 65536  .. 98303
// h lo:                                            : 98304  .. 131071
// B buf0/buf1: [256n][64k] fp16 128B rows          : 131072 .. 196607
#define SM_AH 0
#define SM_HH 65536
#define SM_B  131072
#define SMEM_TOTAL 196608

// ---------------- device scratch ----------------------------------------------
__device__ __align__(16) float g_imgT[SPATIAL * C_C];     // img batch0 [pixel][chan]
__device__ unsigned g_keys[BB * CH_ALL];
__device__ __align__(16) float g_hid[2][BB][CH_HID];
__device__ __align__(16) float g_att_l[BB * C_L];
__device__ __align__(16) float g_att_c[BB * C_C];
// pre-swizzled fp16 weight images: 4 panels x 32KB ([256n][64k] 128B rows)
__device__ __align__(16) __half g_B1[65536];              // 128KB
__device__ __align__(16) __half g_B2[65536];

// ---------------- helpers -------------------------------------------------------
__device__ __forceinline__ u32 smem_u32(const void* p) {
    u32 r;
    asm("{ .reg .u64 t; cvta.to.shared.u64 t, %1; cvt.u32.u64 %0, t; }" : "=r"(r) : "l"(p));
    return r;
}
__device__ __forceinline__ void cp16(u32 dst, const void* src) {
    asm volatile("cp.async.cg.shared.global [%0], [%1], 16;" :: "r"(dst), "l"(src) : "memory");
}
__device__ __forceinline__ void cp_commit() { asm volatile("cp.async.commit_group;" ::: "memory"); }
__device__ __forceinline__ void cp_wait0()  { asm volatile("cp.async.wait_group 0;" ::: "memory"); }
__device__ __forceinline__ void cp_wait1()  { asm volatile("cp.async.wait_group 1;" ::: "memory"); }

__device__ __forceinline__ void ldsm4(u32 a, u32 &r0, u32 &r1, u32 &r2, u32 &r3) {
    asm volatile("ldmatrix.sync.aligned.m8n8.x4.shared.b16 {%0,%1,%2,%3}, [%4];"
                 : "=r"(r0), "=r"(r1), "=r"(r2), "=r"(r3) : "r"(a));
}
__device__ __forceinline__ void mma16816(float* c, const u32* a, u32 b0, u32 b1) {
    asm volatile("mma.sync.aligned.m16n8k16.row.col.f32.f16.f16.f32 "
                 "{%0,%1,%2,%3}, {%4,%5,%6,%7}, {%8,%9}, {%0,%1,%2,%3};"
                 : "+f"(c[0]), "+f"(c[1]), "+f"(c[2]), "+f"(c[3])
                 : "r"(a[0]), "r"(a[1]), "r"(a[2]), "r"(a[3]), "r"(b0), "r"(b1));
}

// fp16 hi/lo split of a fp32 pair into two f16x2 words (low16 = v0)
__device__ __forceinline__ void split2h(float v0, float v1, u32 &h, u32 &l) {
    __half2 hh = __floats2half2_rn(v0, v1);
    h = *(u32*)&hh;
    float r0 = v0 - __low2float(hh);
    float r1 = v1 - __high2float(hh);
    __half2 ll = __floats2half2_rn(r0, r1);
    l = *(u32*)&ll;
}

// Order-preserving float <-> uint encoding for atomic min/max
__device__ __forceinline__ unsigned enc_f(float x) {
    unsigned u = __float_as_uint(x);
    return (u & 0x80000000u) ? ~u : (u | 0x80000000u);
}
__device__ __forceinline__ float dec_f(unsigned k) {
    unsigned u = (k & 0x80000000u) ? (k ^ 0x80000000u) : ~k;
    return __uint_as_float(u);
}

// ---------------- kernel 0: init min/max keys -----------------------------------
__global__ void init_keys_kernel() {
    int i = blockIdx.x * blockDim.x + threadIdx.x;
    if (i >= BB * CH_ALL) return;
    int slot = i & (CH_ALL - 1);
    bool is_min = (slot < 128) || (slot >= 256 && slot < 384);
    g_keys[i] = is_min ? 0xFFFFFFFFu : 0x00000000u;
}

// ---------------- kernel 1: transpose img_bev[0] [C][P] -> [P][C] ---------------
__global__ void transpose_kernel(const float* __restrict__ img) {
    __shared__ float tile[32][33];
    int p0 = blockIdx.x * 32;
    int c0 = blockIdx.y * 32;
    int tx = threadIdx.x, ty = threadIdx.y;
#pragma unroll
    for (int j = 0; j < 4; ++j) {
        int c = c0 + ty + j * 8;
        int p = p0 + tx;
        if (p < SPATIAL) tile[ty + j * 8][tx] = img[c * SPATIAL + p];
    }
    __syncthreads();
#pragma unroll
    for (int j = 0; j < 4; ++j) {
        int p = p0 + ty + j * 8;
        int c = c0 + tx;
        if (p < SPATIAL) g_imgT[p * C_C + c] = tile[tx][ty + j * 8];
    }
}

// ---------------- kernel 2: per-batch segment min/max ---------------------------
// 256-row chunks (grid 625, good occupancy) + 8-chain ILP on uniform chunks.
#define MM_CHUNK 256
__device__ __forceinline__ void flush_mm(int b, int c, float mn, float mx) {
    int msl, xsl;
    if (c < 128) { msl = c;             xsl = 128 + c; }
    else         { msl = 256 + c - 128; xsl = 384 + c - 128; }
    atomicMin(&g_keys[b * CH_ALL + msl], enc_f(mn));
    atomicMax(&g_keys[b * CH_ALL + xsl], enc_f(mx));
}
__global__ void __launch_bounds__(256) minmax_kernel(
    const float* __restrict__ lidar, const int* __restrict__ batch_idx,
    const int* __restrict__ y_idx, const int* __restrict__ x_idx, int N)
{
    __shared__ int sb[MM_CHUNK];
    __shared__ int sr[MM_CHUNK];
    int tid = threadIdx.x;
    int n0 = blockIdx.x * MM_CHUNK;
    int cnt = N - n0; if (cnt > MM_CHUNK) cnt = MM_CHUNK;
    if (cnt <= 0) return;
    if (tid < cnt) {
        int n = n0 + tid;
        int b = batch_idx[n];
        int r = b * SPATIAL + y_idx[n] * WW + x_idx[n];
        if (r > SPATIAL - 2) r = SPATIAL - 2;
        sb[tid] = b; sr[tid] = r;
    }
    __syncthreads();
    const int c = tid;
    const bool cam = (c >= 128);
    const float* base = cam ? (g_imgT + (c - 128)) : (lidar + c);

    if (sb[0] == sb[cnt - 1]) {
        // uniform chunk: 8 independent chains for memory-level parallelism
        float mn[8], mx[8];
#pragma unroll
        for (int q = 0; q < 8; ++q) { mn[q] = INFINITY; mx[q] = -INFINITY; }
        int i = 0;
        for (; i + 8 <= cnt; i += 8) {
            float v[8];
#pragma unroll
            for (int q = 0; q < 8; ++q)
                v[q] = cam ? base[(size_t)sr[i + q] * C_C]
                           : base[(size_t)(n0 + i + q) * C_L];
#pragma unroll
            for (int q = 0; q < 8; ++q) {
                mn[q] = fminf(mn[q], v[q]);
                mx[q] = fmaxf(mx[q], v[q]);
            }
        }
        for (; i < cnt; ++i) {
            float v = cam ? base[(size_t)sr[i] * C_C] : base[(size_t)(n0 + i) * C_L];
            mn[0] = fminf(mn[0], v); mx[0] = fmaxf(mx[0], v);
        }
#pragma unroll
        for (int q = 1; q < 8; ++q) {
            mn[0] = fminf(mn[0], mn[q]);
            mx[0] = fmaxf(mx[0], mx[q]);
        }
        flush_mm(sb[0], c, mn[0], mx[0]);
    } else {
        // rare chunk containing a batch boundary
        float mn = INFINITY, mx = -INFINITY;
        int cur = sb[0];
        for (int i = 0; i < cnt; ++i) {
            int b = sb[i];
            if (b != cur) { flush_mm(cur, c, mn, mx); cur = b; mn = INFINITY; mx = -INFINITY; }
            float v = cam ? base[(size_t)sr[i] * C_C] : base[(size_t)(n0 + i) * C_L];
            mn = fminf(mn, v); mx = fmaxf(mx, v);
        }
        flush_mm(cur, c, mn, mx);
    }
}

// ---------------- kernel 3a/3b: tiny gating MLPs --------------------------------
__global__ void __launch_bounds__(256) mlp1_kernel(
    const float* __restrict__ Wl1, const float* __restrict__ Wc1)
{
    int gw   = blockIdx.x * 8 + (threadIdx.x >> 5);
    int lane = threadIdx.x & 31;
    int net  = gw / (BB * CH_HID);
    int rem  = gw % (BB * CH_HID);
    int b    = rem / CH_HID;
    int j    = rem % CH_HID;
    const float* W = net ? Wc1 : Wl1;
    float s = 0.f;
#pragma unroll
    for (int t = 0; t < 16; ++t) {
        int k = lane + 32 * t;
        s = fmaf(dec_f(g_keys[b * CH_ALL + k]), W[k * CH_HID + j], s);
    }
#pragma unroll
    for (int o = 16; o; o >>= 1) s += __shfl_xor_sync(0xffffffffu, s, o);
    if (lane == 0) g_hid[net][b][j] = fmaxf(s, 0.f);
}
__global__ void __launch_bounds__(256) mlp2_kernel(
    const float* __restrict__ Wl2, const float* __restrict__ Wc2)
{
    int idx = blockIdx.x * 256 + threadIdx.x;
    int net = idx >> 9, rem = idx & 511;
    int b = rem >> 7, cc = rem & 127;
    const float* W2 = net ? Wc2 : Wl2;
    const float* h  = g_hid[net][b];
    float s = 0.f;
    for (int k = 0; k < CH_HID; ++k) s = fmaf(h[k], W2[k * 128 + cc], s);
    float v = fmaxf(s, 0.f);
    (net ? g_att_c : g_att_l)[b * 128 + cc] = 1.f / (1.f + expf(-v));
}

// ---------------- kernel 3c: weight prep (transpose + fp16 + pre-swizzle) -------
// Image: panel p (k in [64p, 64p+64)), row n (128B = 8 units of 16B), unit holds
// 8 consecutive k (k8l = (k>>3)&7), stored unit = k8l ^ (n & 7).
__global__ void __launch_bounds__(256) weight_prep_kernel(
    const float* __restrict__ Wf1, const float* __restrict__ Wf2)
{
    int idx = blockIdx.x * 256 + threadIdx.x;   // 2 * 65536
    int mat = idx >> 16;
    int rem = idx & 65535;
    int k = rem >> 8;          // 0..255 input dim
    int n = rem & 255;         // 0..255 output dim
    const float* W = mat ? Wf2 : Wf1;
    __half hv = __float2half_rn(W[k * 256 + n]);
    int p = k >> 6, k8l = (k >> 3) & 7, e = k & 7;
    u32 off = (u32)p * 32768u + (u32)n * 128u + ((u32)(k8l ^ (n & 7)) << 4) + (u32)e * 2u;
    __half* img = mat ? g_B2 : g_B1;
    *(unsigned short*)((char*)img + off) = *(unsigned short*)&hv;
}

// ---------------- fused GEMM stage (M=64, fp16 2-term) ----------------------------
// acc += (Ahi+Alo) x B, K=256 in 4 panels of 64, cp.async double-buffered.
// Warp tile 32m x 64n (8 warps: 2m x 4n).
__device__ __forceinline__ void gemm_stage(
    u32 smb, u32 Abase, const uint4* __restrict__ Bimg,
    float acc[2][8][4], int tid, int lane, int wm, int wn)
{
    const u32 Bb = smb + SM_B;
    // preload panel 0 -> buf0
    {
        u32 dst = Bb + (u32)tid * 16u;
        const uint4* s = Bimg + tid;
#pragma unroll
        for (int i = 0; i < 8; ++i) cp16(dst + i * 4096u, s + i * 256);
        cp_commit();
    }
#pragma unroll 1
    for (int p = 0; p < 4; ++p) {
        if (p < 3) {
            u32 dst = Bb + (u32)((p + 1) & 1) * 32768u + (u32)tid * 16u;
            const uint4* s = Bimg + (p + 1) * 2048 + tid;
#pragma unroll
            for (int i = 0; i < 8; ++i) cp16(dst + i * 4096u, s + i * 256);
            cp_commit();
            cp_wait1();
        } else {
            cp_wait0();
        }
        __syncthreads();
        u32 B = Bb + (u32)(p & 1) * 32768u;
#pragma unroll
        for (int s = 0; s < 4; ++s) {
            int k8 = p * 8 + s * 2 + (lane >> 4);    // A unit index 0..31
            int arow = wm + (lane & 15);
            u32 aoff = (u32)arow * 512u + ((u32)(k8 ^ (arow & 7)) << 4);
            // ---- A hi fragments: 2 m16 tiles ----
            u32 ah[2][4], al[2][4];
            ldsm4(Abase + aoff,          ah[0][0], ah[0][1], ah[0][2], ah[0][3]);
            ldsm4(Abase + aoff + 8192u,  ah[1][0], ah[1][1], ah[1][2], ah[1][3]);
            // ---- B fragments: 8 n8 ----
            int k8h = s * 2 + (lane >> 4);           // 0..7
            u32 bh[8][2];
#pragma unroll
            for (int j16 = 0; j16 < 4; ++j16) {
                int brow = wn + j16 * 16 + (lane & 15);
                u32 rb = B + (u32)brow * 128u;
                u32 r0, r1, r2, r3;
                ldsm4(rb + ((u32)(k8h ^ (brow & 7)) << 4), r0, r1, r2, r3);
                bh[2*j16][0] = r0;   bh[2*j16][1] = r2;
                bh[2*j16+1][0] = r1; bh[2*j16+1][1] = r3;
            }
            // term 1: Ah x B
#pragma unroll
            for (int t = 0; t < 2; ++t)
#pragma unroll
                for (int j = 0; j < 8; ++j)
                    mma16816(acc[t][j], ah[t], bh[j][0], bh[j][1]);
            // ---- A lo fragments ----
            ldsm4(Abase + 32768u + aoff,         al[0][0], al[0][1], al[0][2], al[0][3]);
            ldsm4(Abase + 32768u + aoff + 8192u, al[1][0], al[1][1], al[1][2], al[1][3]);
            // term 2: Al x B
#pragma unroll
            for (int t = 0; t < 2; ++t)
#pragma unroll
                for (int j = 0; j < 8; ++j)
                    mma16816(acc[t][j], al[t], bh[j][0], bh[j][1]);
        }
        __syncthreads();
    }
}

// ---------------- kernel 4: fused gate + GEMM1 + ReLU + GEMM2 + ReLU -------------
__global__ void __launch_bounds__(256, 1) fused_mma_kernel(
    const float* __restrict__ lidar,
    const int* __restrict__ batch_idx,
    const int* __restrict__ y_idx,
    const int* __restrict__ x_idx,
    float* __restrict__ out, int N)
{
    extern __shared__ char sm[];
    const u32 smb = smem_u32(sm);
    const int tid  = threadIdx.x;
    const int lane = tid & 31;
    const int wid  = tid >> 5;
    const int wm   = (wid & 1) * 32;
    const int wn   = (wid >> 1) * 64;

    // ---- phase 1: gather + gate + fp16 split into A smem (swizzled) ----
    {
        int m = tid >> 2, q = tid & 3;          // 4 threads per row, 64 ch each
        int n = blockIdx.x * 64 + m;
        int nn = n < N ? n : N - 1;
        int b = batch_idx[nn];
        const float* src;
        const float* att;
        if (q < 2) { src = lidar + (size_t)nn * C_L; att = g_att_l + b * 128; }
        else {
            int r = b * SPATIAL + y_idx[nn] * WW + x_idx[nn];
            if (r > SPATIAL - 2) r = SPATIAL - 2;
            src = g_imgT + (size_t)r * C_C; att = g_att_c + b * 128;
        }
        const float4* s4 = (const float4*)src;
        const float4* g4 = (const float4*)att;
        int ho = (q & 1) * 16;                   // float4 offset within source
        u32 rowb = (u32)m * 512u;
        u32 xm = (u32)(m & 7);
#pragma unroll
        for (int i = 0; i < 8; ++i) {
            float4 a0 = s4[ho + 2*i], a1 = s4[ho + 2*i + 1];
            float4 q0 = g4[ho + 2*i], q1 = g4[ho + 2*i + 1];
            float v0 = a0.x*q0.x, v1 = a0.y*q0.y, v2 = a0.z*q0.z, v3 = a0.w*q0.w;
            float v4 = a1.x*q1.x, v5 = a1.y*q1.y, v6 = a1.z*q1.z, v7 = a1.w*q1.w;
            uint4 H, L;
            split2h(v0, v1, H.x, L.x); split2h(v2, v3, H.y, L.y);
            split2h(v4, v5, H.z, L.z); split2h(v6, v7, H.w, L.w);
            u32 k8 = (u32)(q * 8 + i);          // 0..31
            u32 off = rowb + ((k8 ^ xm) << 4);
            *(uint4*)(sm + SM_AH + off) = H;
            *(uint4*)(sm + SM_AH + 32768 + off) = L;
        }
    }
    // (first __syncthreads inside gemm_stage covers A writes)

    float acc[2][8][4];
#pragma unroll
    for (int t = 0; t < 2; ++t)
#pragma unroll
        for (int j = 0; j < 8; ++j)
#pragma unroll
            for (int c = 0; c < 4; ++c) acc[t][j][c] = 0.f;

    // ---- GEMM1 ----
    gemm_stage(smb, smb + SM_AH, (const uint4*)g_B1, acc, tid, lane, wm, wn);

    // ---- epilogue 1: relu + fp16 split -> h smem ----
    {
#pragma unroll
        for (int t = 0; t < 2; ++t) {
            int r0 = wm + 16 * t + (lane >> 2);
            int r1 = r0 + 8;
#pragma unroll
            for (int j = 0; j < 8; ++j) {
                float* c = acc[t][j];
                u32 k8 = (u32)((wn >> 3) + j);
                u32 eb = (u32)(lane & 3) * 4u;
                float v0 = fmaxf(c[0], 0.f), v1 = fmaxf(c[1], 0.f);
                float v2 = fmaxf(c[2], 0.f), v3 = fmaxf(c[3], 0.f);
                u32 h0, l0, h1, l1;
                split2h(v0, v1, h0, l0);
                split2h(v2, v3, h1, l1);
                u32 o0 = (u32)r0 * 512u + ((k8 ^ (u32)(r0 & 7)) << 4) + eb;
                u32 o1 = (u32)r1 * 512u + ((k8 ^ (u32)(r1 & 7)) << 4) + eb;
                *(u32*)(sm + SM_HH + o0) = h0;
                *(u32*)(sm + SM_HH + 32768 + o0) = l0;
                *(u32*)(sm + SM_HH + o1) = h1;
                *(u32*)(sm + SM_HH + 32768 + o1) = l1;
            }
        }
    }
    __syncthreads();

#pragma unroll
    for (int t = 0; t < 2; ++t)
#pragma unroll
        for (int j = 0; j < 8; ++j)
#pragma unroll
            for (int c = 0; c < 4; ++c) acc[t][j][c] = 0.f;

    // ---- GEMM2 ----
    gemm_stage(smb, smb + SM_HH, (const uint4*)g_B2, acc, tid, lane, wm, wn);

    // ---- epilogue 2: relu -> gmem ----
    {
        int mbase = blockIdx.x * 64;
#pragma unroll
        for (int t = 0; t < 2; ++t) {
            int r0 = mbase + wm + 16 * t + (lane >> 2);
            int r1 = r0 + 8;
#pragma unroll
            for (int j = 0; j < 8; ++j) {
                float* c = acc[t][j];
                int col = wn + 8 * j + 2 * (lane & 3);
                if (r0 < N) {
                    float2 v = make_float2(fmaxf(c[0], 0.f), fmaxf(c[1], 0.f));
                    *(float2*)(out + (size_t)r0 * 256 + col) = v;
                }
                if (r1 < N) {
                    float2 v = make_float2(fmaxf(c[2], 0.f), fmaxf(c[3], 0.f));
                    *(float2*)(out + (size_t)r1 * 256 + col) = v;
                }
            }
        }
    }
}

// ---------------- host launcher ---------------------------------------------------
extern "C" void kernel_launch(void* const* d_in, const int* in_sizes, int n_in,
                              void* d_out, int out_size)
{
    int iL = -1, iImg = -1, iB = -1, iY = -1, iX = -1;
    int iWl1 = -1, iWl2 = -1, iWc1 = -1, iWc2 = -1, iWf1 = -1, iWf2 = -1;
    for (int i = 0; i < n_in; ++i) {
        int s = in_sizes[i];
        if      (s == BB * C_C * SPATIAL)      iImg = i;
        else if (s == CH_ALL * CH_HID)         { if (iWl1 < 0) iWl1 = i; else iWc1 = i; }
        else if (s == CH_HID * C_L)            { if (iWl2 < 0) iWl2 = i; else iWc2 = i; }
        else if (s == C_OUT * C_OUT)           { if (iWf1 < 0) iWf1 = i; else iWf2 = i; }
        else if (s % C_L == 0 && s >= 1000000) iL = i;
        else                                   { if (iB < 0) iB = i; else if (iY < 0) iY = i; else iX = i; }
    }
    const float* lidar = (const float*)d_in[iL];
    const float* img   = (const float*)d_in[iImg];
    const int*   bidx  = (const int*)d_in[iB];
    const int*   yidx  = (const int*)d_in[iY];
    const int*   xidx  = (const int*)d_in[iX];
    const float* Wl1   = (const float*)d_in[iWl1];
    const float* Wl2   = (const float*)d_in[iWl2];
    const float* Wc1   = (const float*)d_in[iWc1];
    const float* Wc2   = (const float*)d_in[iWc2];
    const float* Wf1   = (const float*)d_in[iWf1];
    const float* Wf2   = (const float*)d_in[iWf2];
    float* out = (float*)d_out;
    const int N = in_sizes[iL] / C_L;

    cudaFuncSetAttribute(fused_mma_kernel, cudaFuncAttributeMaxDynamicSharedMemorySize, SMEM_TOTAL);

    init_keys_kernel<<<(BB * CH_ALL + 255) / 256, 256>>>();
    transpose_kernel<<<dim3((SPATIAL + 31) / 32, C_C / 32), dim3(32, 8)>>>(img);
    weight_prep_kernel<<<512, 256>>>(Wf1, Wf2);
    minmax_kernel<<<(N + MM_CHUNK - 1) / MM_CHUNK, 256>>>(lidar, bidx, yidx, xidx, N);
    mlp1_kernel<<<CH_HID, 256>>>(Wl1, Wc1);
    mlp2_kernel<<<4, 256>>>(Wl2, Wc2);
    fused_mma_kernel<<<(N + 63) / 64, 256, SMEM_TOTAL>>>(lidar, bidx, yidx, xidx, out, N);
    (void)out_size;
}

// round 7
// speedup vs baseline: 2.9845x; 1.2952x over previous
#include <cuda_runtime.h>
#include <cuda_fp16.h>
#include <math.h>

// Problem constants (fixed-shape problem)
#define BB 4
#define HH_ 180
#define WW 180
#define SPATIAL (HH_ * WW)       // 32400
#define C_L 128
#define C_C 128
#define CH_ALL 512
#define CH_HID 170
#define C_OUT 256

typedef unsigned int u32;
typedef unsigned long long u64;

// ---- fused kernel smem map (bytes) ----
// A: [64m][256k] fp16, 512B rows, xor-swizzled : 0     .. 32767
// h: same layout                                : 32768 .. 65535
// B buf0/buf1: [256n][64k] fp16 128B rows       : 65536 .. 131071
#define SM_AH 0
#define SM_HH 32768
#define SM_B  65536
#define SMEM_TOTAL 131072

// ---------------- device scratch ----------------------------------------------
__device__ __align__(16) float g_imgT[SPATIAL * C_C];     // img batch0 [pixel][chan]
__device__ unsigned g_keys[BB * CH_ALL];
__device__ __align__(16) float g_hid[2][BB][CH_HID];
__device__ __align__(16) float g_att_l[BB * C_L];
__device__ __align__(16) float g_att_c[BB * C_C];
// pre-swizzled fp16 weight images: 4 panels x 32KB ([256n][64k] 128B rows)
__device__ __align__(16) __half g_B1[65536];              // 128KB
__device__ __align__(16) __half g_B2[65536];

// ---------------- helpers -------------------------------------------------------
__device__ __forceinline__ u32 smem_u32(const void* p) {
    u32 r;
    asm("{ .reg .u64 t; cvta.to.shared.u64 t, %1; cvt.u32.u64 %0, t; }" : "=r"(r) : "l"(p));
    return r;
}
__device__ __forceinline__ void cp16(u32 dst, const void* src) {
    asm volatile("cp.async.cg.shared.global [%0], [%1], 16;" :: "r"(dst), "l"(src) : "memory");
}
__device__ __forceinline__ void cp_commit() { asm volatile("cp.async.commit_group;" ::: "memory"); }
__device__ __forceinline__ void cp_wait0()  { asm volatile("cp.async.wait_group 0;" ::: "memory"); }
__device__ __forceinline__ void cp_wait1()  { asm volatile("cp.async.wait_group 1;" ::: "memory"); }

__device__ __forceinline__ void ldsm4(u32 a, u32 &r0, u32 &r1, u32 &r2, u32 &r3) {
    asm volatile("ldmatrix.sync.aligned.m8n8.x4.shared.b16 {%0,%1,%2,%3}, [%4];"
                 : "=r"(r0), "=r"(r1), "=r"(r2), "=r"(r3) : "r"(a));
}
__device__ __forceinline__ void mma16816(float* c, const u32* a, u32 b0, u32 b1) {
    asm volatile("mma.sync.aligned.m16n8k16.row.col.f32.f16.f16.f32 "
                 "{%0,%1,%2,%3}, {%4,%5,%6,%7}, {%8,%9}, {%0,%1,%2,%3};"
                 : "+f"(c[0]), "+f"(c[1]), "+f"(c[2]), "+f"(c[3])
                 : "r"(a[0]), "r"(a[1]), "r"(a[2]), "r"(a[3]), "r"(b0), "r"(b1));
}

// Order-preserving float <-> uint encoding for atomic min/max
__device__ __forceinline__ unsigned enc_f(float x) {
    unsigned u = __float_as_uint(x);
    return (u & 0x80000000u) ? ~u : (u | 0x80000000u);
}
__device__ __forceinline__ float dec_f(unsigned k) {
    unsigned u = (k & 0x80000000u) ? (k ^ 0x80000000u) : ~k;
    return __uint_as_float(u);
}
__device__ __forceinline__ void min4(float4 &d, float4 v) {
    d.x = fminf(d.x, v.x); d.y = fminf(d.y, v.y);
    d.z = fminf(d.z, v.z); d.w = fminf(d.w, v.w);
}
__device__ __forceinline__ void max4(float4 &d, float4 v) {
    d.x = fmaxf(d.x, v.x); d.y = fmaxf(d.y, v.y);
    d.z = fmaxf(d.z, v.z); d.w = fmaxf(d.w, v.w);
}

// ---------------- kernel 0: init min/max keys -----------------------------------
__global__ void init_keys_kernel() {
    int i = blockIdx.x * blockDim.x + threadIdx.x;
    if (i >= BB * CH_ALL) return;
    int slot = i & (CH_ALL - 1);
    bool is_min = (slot < 128) || (slot >= 256 && slot < 384);
    g_keys[i] = is_min ? 0xFFFFFFFFu : 0x00000000u;
}

// ---------------- kernel 1: transpose img_bev[0] [C][P] -> [P][C] ---------------
__global__ void transpose_kernel(const float* __restrict__ img) {
    __shared__ float tile[32][33];
    int p0 = blockIdx.x * 32;
    int c0 = blockIdx.y * 32;
    int tx = threadIdx.x, ty = threadIdx.y;
#pragma unroll
    for (int j = 0; j < 4; ++j) {
        int c = c0 + ty + j * 8;
        int p = p0 + tx;
        if (p < SPATIAL) tile[ty + j * 8][tx] = img[c * SPATIAL + p];
    }
    __syncthreads();
#pragma unroll
    for (int j = 0; j < 4; ++j) {
        int p = p0 + ty + j * 8;
        int c = c0 + tx;
        if (p < SPATIAL) g_imgT[p * C_C + c] = tile[tx][ty + j * 8];
    }
}

// ---------------- kernel 2: per-batch segment min/max ---------------------------
// 256-row chunks; uniform chunks take a float4-vectorized path (warp = one row,
// 8 row-groups in parallel, smem tree reduce). Boundary chunks: scalar path.
#define MM_CHUNK 256
__device__ __forceinline__ void flush_mm(int b, int c, float mn, float mx) {
    int msl, xsl;
    if (c < 128) { msl = c;             xsl = 128 + c; }
    else         { msl = 256 + c - 128; xsl = 384 + c - 128; }
    atomicMin(&g_keys[b * CH_ALL + msl], enc_f(mn));
    atomicMax(&g_keys[b * CH_ALL + xsl], enc_f(mx));
}
__global__ void __launch_bounds__(256) minmax_kernel(
    const float* __restrict__ lidar, const int* __restrict__ batch_idx,
    const int* __restrict__ y_idx, const int* __restrict__ x_idx, int N)
{
    __shared__ int sb[MM_CHUNK];
    __shared__ int sr[MM_CHUNK];
    __shared__ float red[4][8][128];
    int tid = threadIdx.x;
    int n0 = blockIdx.x * MM_CHUNK;
    int cnt = N - n0; if (cnt > MM_CHUNK) cnt = MM_CHUNK;
    if (cnt <= 0) return;
    if (tid < cnt) {
        int n = n0 + tid;
        int b = batch_idx[n];
        int r = b * SPATIAL + y_idx[n] * WW + x_idx[n];
        if (r > SPATIAL - 2) r = SPATIAL - 2;
        sb[tid] = b; sr[tid] = r;
    }
    __syncthreads();

    if (cnt == MM_CHUNK && sb[0] == sb[MM_CHUNK - 1]) {
        // ---- vectorized uniform path ----
        const int rg = tid >> 5;   // row-group 0..7
        const int c4 = tid & 31;   // float4 channel group
        const float4* lid4 = (const float4*)lidar;
        const float4* img4 = (const float4*)g_imgT;
        float4 mnl = make_float4( INFINITY,  INFINITY,  INFINITY,  INFINITY);
        float4 mxl = make_float4(-INFINITY, -INFINITY, -INFINITY, -INFINITY);
        float4 mnc = mnl, mxc = mxl;
#pragma unroll 4
        for (int i = 0; i < 32; ++i) {
            int row = i * 8 + rg;
            float4 lv = lid4[(size_t)(n0 + row) * 32 + c4];
            float4 cv = img4[(size_t)sr[row] * 32 + c4];
            min4(mnl, lv); max4(mxl, lv);
            min4(mnc, cv); max4(mxc, cv);
        }
        int ch = c4 * 4;
        *(float4*)&red[0][rg][ch] = mnl;
        *(float4*)&red[1][rg][ch] = mxl;
        *(float4*)&red[2][rg][ch] = mnc;
        *(float4*)&red[3][rg][ch] = mxc;
        __syncthreads();
        int c = tid;
        int qm = (c < 128) ? 0 : 2;
        int cc = c & 127;
        float mn = red[qm][0][cc], mx = red[qm + 1][0][cc];
#pragma unroll
        for (int g = 1; g < 8; ++g) {
            mn = fminf(mn, red[qm][g][cc]);
            mx = fmaxf(mx, red[qm + 1][g][cc]);
        }
        flush_mm(sb[0], c, mn, mx);
    } else {
        // ---- boundary / tail chunk: scalar path ----
        const int c = tid;
        const bool cam = (c >= 128);
        const float* base = cam ? (g_imgT + (c - 128)) : (lidar + c);
        float mn = INFINITY, mx = -INFINITY;
        int cur = sb[0];
        for (int i = 0; i < cnt; ++i) {
            int b = sb[i];
            if (b != cur) { flush_mm(cur, c, mn, mx); cur = b; mn = INFINITY; mx = -INFINITY; }
            float v = cam ? base[(size_t)sr[i] * C_C] : base[(size_t)(n0 + i) * C_L];
            mn = fminf(mn, v); mx = fmaxf(mx, v);
        }
        flush_mm(cur, c, mn, mx);
    }
}

// ---------------- kernel 3a/3b: tiny gating MLPs --------------------------------
__global__ void __launch_bounds__(256) mlp1_kernel(
    const float* __restrict__ Wl1, const float* __restrict__ Wc1)
{
    int gw   = blockIdx.x * 8 + (threadIdx.x >> 5);
    int lane = threadIdx.x & 31;
    int net  = gw / (BB * CH_HID);
    int rem  = gw % (BB * CH_HID);
    int b    = rem / CH_HID;
    int j    = rem % CH_HID;
    const float* W = net ? Wc1 : Wl1;
    float s = 0.f;
#pragma unroll
    for (int t = 0; t < 16; ++t) {
        int k = lane + 32 * t;
        s = fmaf(dec_f(g_keys[b * CH_ALL + k]), W[k * CH_HID + j], s);
    }
#pragma unroll
    for (int o = 16; o; o >>= 1) s += __shfl_xor_sync(0xffffffffu, s, o);
    if (lane == 0) g_hid[net][b][j] = fmaxf(s, 0.f);
}
__global__ void __launch_bounds__(256) mlp2_kernel(
    const float* __restrict__ Wl2, const float* __restrict__ Wc2)
{
    int idx = blockIdx.x * 256 + threadIdx.x;
    int net = idx >> 9, rem = idx & 511;
    int b = rem >> 7, cc = rem & 127;
    const float* W2 = net ? Wc2 : Wl2;
    const float* h  = g_hid[net][b];
    float s = 0.f;
    for (int k = 0; k < CH_HID; ++k) s = fmaf(h[k], W2[k * 128 + cc], s);
    float v = fmaxf(s, 0.f);
    (net ? g_att_c : g_att_l)[b * 128 + cc] = 1.f / (1.f + expf(-v));
}

// ---------------- kernel 3c: weight prep (transpose + fp16 + pre-swizzle) -------
__global__ void __launch_bounds__(256) weight_prep_kernel(
    const float* __restrict__ Wf1, const float* __restrict__ Wf2)
{
    int idx = blockIdx.x * 256 + threadIdx.x;   // 2 * 65536
    int mat = idx >> 16;
    int rem = idx & 65535;
    int k = rem >> 8;          // 0..255 input dim
    int n = rem & 255;         // 0..255 output dim
    const float* W = mat ? Wf2 : Wf1;
    __half hv = __float2half_rn(W[k * 256 + n]);
    int p = k >> 6, k8l = (k >> 3) & 7, e = k & 7;
    u32 off = (u32)p * 32768u + (u32)n * 128u + ((u32)(k8l ^ (n & 7)) << 4) + (u32)e * 2u;
    __half* img = mat ? g_B2 : g_B1;
    *(unsigned short*)((char*)img + off) = *(unsigned short*)&hv;
}

// ---------------- fused GEMM stage (M=64, fp16 single-term) ------------------------
// acc += A x B, K=256 in 4 panels of 64, cp.async double-buffered.
// Warp tile 32m x 64n (8 warps: 2m x 4n).
__device__ __forceinline__ void gemm_stage(
    u32 smb, u32 Abase, const uint4* __restrict__ Bimg,
    float acc[2][8][4], int tid, int lane, int wm, int wn)
{
    const u32 Bb = smb + SM_B;
    // preload panel 0 -> buf0
    {
        u32 dst = Bb + (u32)tid * 16u;
        const uint4* s = Bimg + tid;
#pragma unroll
        for (int i = 0; i < 8; ++i) cp16(dst + i * 4096u, s + i * 256);
        cp_commit();
    }
#pragma unroll 1
    for (int p = 0; p < 4; ++p) {
        if (p < 3) {
            u32 dst = Bb + (u32)((p + 1) & 1) * 32768u + (u32)tid * 16u;
            const uint4* s = Bimg + (p + 1) * 2048 + tid;
#pragma unroll
            for (int i = 0; i < 8; ++i) cp16(dst + i * 4096u, s + i * 256);
            cp_commit();
            cp_wait1();
        } else {
            cp_wait0();
        }
        __syncthreads();
        u32 B = Bb + (u32)(p & 1) * 32768u;
#pragma unroll
        for (int s = 0; s < 4; ++s) {
            int k8 = p * 8 + s * 2 + (lane >> 4);    // A unit index 0..31
            int arow = wm + (lane & 15);
            u32 aoff = (u32)arow * 512u + ((u32)(k8 ^ (arow & 7)) << 4);
            // ---- A fragments: 2 m16 tiles ----
            u32 ah[2][4];
            ldsm4(Abase + aoff,          ah[0][0], ah[0][1], ah[0][2], ah[0][3]);
            ldsm4(Abase + aoff + 8192u,  ah[1][0], ah[1][1], ah[1][2], ah[1][3]);
            // ---- B fragments: 8 n8 ----
            int k8h = s * 2 + (lane >> 4);           // 0..7
            u32 bh[8][2];
#pragma unroll
            for (int j16 = 0; j16 < 4; ++j16) {
                int brow = wn + j16 * 16 + (lane & 15);
                u32 rb = B + (u32)brow * 128u;
                u32 r0, r1, r2, r3;
                ldsm4(rb + ((u32)(k8h ^ (brow & 7)) << 4), r0, r1, r2, r3);
                bh[2*j16][0] = r0;   bh[2*j16][1] = r2;
                bh[2*j16+1][0] = r1; bh[2*j16+1][1] = r3;
            }
#pragma unroll
            for (int t = 0; t < 2; ++t)
#pragma unroll
                for (int j = 0; j < 8; ++j)
                    mma16816(acc[t][j], ah[t], bh[j][0], bh[j][1]);
        }
        __syncthreads();
    }
}

// ---------------- kernel 4: fused gate + GEMM1 + ReLU + GEMM2 + ReLU -------------
__global__ void __launch_bounds__(256, 1) fused_mma_kernel(
    const float* __restrict__ lidar,
    const int* __restrict__ batch_idx,
    const int* __restrict__ y_idx,
    const int* __restrict__ x_idx,
    float* __restrict__ out, int N)
{
    extern __shared__ char sm[];
    const u32 smb = smem_u32(sm);
    const int tid  = threadIdx.x;
    const int lane = tid & 31;
    const int wid  = tid >> 5;
    const int wm   = (wid & 1) * 32;
    const int wn   = (wid >> 1) * 64;

    // ---- phase 1: gather + gate + fp16 cvt into A smem (swizzled) ----
    {
        int m = tid >> 2, q = tid & 3;          // 4 threads per row, 64 ch each
        int n = blockIdx.x * 64 + m;
        int nn = n < N ? n : N - 1;
        int b = batch_idx[nn];
        const float* src;
        const float* att;
        if (q < 2) { src = lidar + (size_t)nn * C_L; att = g_att_l + b * 128; }
        else {
            int r = b * SPATIAL + y_idx[nn] * WW + x_idx[nn];
            if (r > SPATIAL - 2) r = SPATIAL - 2;
            src = g_imgT + (size_t)r * C_C; att = g_att_c + b * 128;
        }
        const float4* s4 = (const float4*)src;
        const float4* g4 = (const float4*)att;
        int ho = (q & 1) * 16;                   // float4 offset within source
        u32 rowb = (u32)m * 512u;
        u32 xm = (u32)(m & 7);
#pragma unroll
        for (int i = 0; i < 8; ++i) {
            float4 a0 = s4[ho + 2*i], a1 = s4[ho + 2*i + 1];
            float4 q0 = g4[ho + 2*i], q1 = g4[ho + 2*i + 1];
            __half2 h0 = __floats2half2_rn(a0.x*q0.x, a0.y*q0.y);
            __half2 h1 = __floats2half2_rn(a0.z*q0.z, a0.w*q0.w);
            __half2 h2 = __floats2half2_rn(a1.x*q1.x, a1.y*q1.y);
            __half2 h3 = __floats2half2_rn(a1.z*q1.z, a1.w*q1.w);
            uint4 H = make_uint4(*(u32*)&h0, *(u32*)&h1, *(u32*)&h2, *(u32*)&h3);
            u32 k8 = (u32)(q * 8 + i);          // 0..31
            u32 off = rowb + ((k8 ^ xm) << 4);
            *(uint4*)(sm + SM_AH + off) = H;
        }
    }
    // (first __syncthreads inside gemm_stage covers A writes)

    float acc[2][8][4];
#pragma unroll
    for (int t = 0; t < 2; ++t)
#pragma unroll
        for (int j = 0; j < 8; ++j)
#pragma unroll
            for (int c = 0; c < 4; ++c) acc[t][j][c] = 0.f;

    // ---- GEMM1 ----
    gemm_stage(smb, smb + SM_AH, (const uint4*)g_B1, acc, tid, lane, wm, wn);

    // ---- epilogue 1: relu + fp16 cvt -> h smem ----
    {
#pragma unroll
        for (int t = 0; t < 2; ++t) {
            int r0 = wm + 16 * t + (lane >> 2);
            int r1 = r0 + 8;
#pragma unroll
            for (int j = 0; j < 8; ++j) {
                float* c = acc[t][j];
                u32 k8 = (u32)((wn >> 3) + j);
                u32 eb = (u32)(lane & 3) * 4u;
                __half2 p0 = __floats2half2_rn(fmaxf(c[0], 0.f), fmaxf(c[1], 0.f));
                __half2 p1 = __floats2half2_rn(fmaxf(c[2], 0.f), fmaxf(c[3], 0.f));
                u32 o0 = (u32)r0 * 512u + ((k8 ^ (u32)(r0 & 7)) << 4) + eb;
                u32 o1 = (u32)r1 * 512u + ((k8 ^ (u32)(r1 & 7)) << 4) + eb;
                *(u32*)(sm + SM_HH + o0) = *(u32*)&p0;
                *(u32*)(sm + SM_HH + o1) = *(u32*)&p1;
            }
        }
    }
    __syncthreads();

#pragma unroll
    for (int t = 0; t < 2; ++t)
#pragma unroll
        for (int j = 0; j < 8; ++j)
#pragma unroll
            for (int c = 0; c < 4; ++c) acc[t][j][c] = 0.f;

    // ---- GEMM2 ----
    gemm_stage(smb, smb + SM_HH, (const uint4*)g_B2, acc, tid, lane, wm, wn);

    // ---- epilogue 2: relu -> gmem ----
    {
        int mbase = blockIdx.x * 64;
#pragma unroll
        for (int t = 0; t < 2; ++t) {
            int r0 = mbase + wm + 16 * t + (lane >> 2);
            int r1 = r0 + 8;
#pragma unroll
            for (int j = 0; j < 8; ++j) {
                float* c = acc[t][j];
                int col = wn + 8 * j + 2 * (lane & 3);
                if (r0 < N) {
                    float2 v = make_float2(fmaxf(c[0], 0.f), fmaxf(c[1], 0.f));
                    *(float2*)(out + (size_t)r0 * 256 + col) = v;
                }
                if (r1 < N) {
                    float2 v = make_float2(fmaxf(c[2], 0.f), fmaxf(c[3], 0.f));
                    *(float2*)(out + (size_t)r1 * 256 + col) = v;
                }
            }
        }
    }
}

// ---------------- host launcher ---------------------------------------------------
extern "C" void kernel_launch(void* const* d_in, const int* in_sizes, int n_in,
                              void* d_out, int out_size)
{
    int iL = -1, iImg = -1, iB = -1, iY = -1, iX = -1;
    int iWl1 = -1, iWl2 = -1, iWc1 = -1, iWc2 = -1, iWf1 = -1, iWf2 = -1;
    for (int i = 0; i < n_in; ++i) {
        int s = in_sizes[i];
        if      (s == BB * C_C * SPATIAL)      iImg = i;
        else if (s == CH_ALL * CH_HID)         { if (iWl1 < 0) iWl1 = i; else iWc1 = i; }
        else if (s == CH_HID * C_L)            { if (iWl2 < 0) iWl2 = i; else iWc2 = i; }
        else if (s == C_OUT * C_OUT)           { if (iWf1 < 0) iWf1 = i; else iWf2 = i; }
        else if (s % C_L == 0 && s >= 1000000) iL = i;
        else                                   { if (iB < 0) iB = i; else if (iY < 0) iY = i; else iX = i; }
    }
    const float* lidar = (const float*)d_in[iL];
    const float* img   = (const float*)d_in[iImg];
    const int*   bidx  = (const int*)d_in[iB];
    const int*   yidx  = (const int*)d_in[iY];
    const int*   xidx  = (const int*)d_in[iX];
    const float* Wl1   = (const float*)d_in[iWl1];
    const float* Wl2   = (const float*)d_in[iWl2];
    const float* Wc1   = (const float*)d_in[iWc1];
    const float* Wc2   = (const float*)d_in[iWc2];
    const float* Wf1   = (const float*)d_in[iWf1];
    const float* Wf2   = (const float*)d_in[iWf2];
    float* out = (float*)d_out;
    const int N = in_sizes[iL] / C_L;

    cudaFuncSetAttribute(fused_mma_kernel, cudaFuncAttributeMaxDynamicSharedMemorySize, SMEM_TOTAL);

    init_keys_kernel<<<(BB * CH_ALL + 255) / 256, 256>>>();
    transpose_kernel<<<dim3((SPATIAL + 31) / 32, C_C / 32), dim3(32, 8)>>>(img);
    weight_prep_kernel<<<512, 256>>>(Wf1, Wf2);
    minmax_kernel<<<(N + MM_CHUNK - 1) / MM_CHUNK, 256>>>(lidar, bidx, yidx, xidx, N);
    mlp1_kernel<<<CH_HID, 256>>>(Wl1, Wc1);
    mlp2_kernel<<<4, 256>>>(Wl2, Wc2);
    fused_mma_kernel<<<(N + 63) / 64, 256, SMEM_TOTAL>>>(lidar, bidx, yidx, xidx, out, N);
    (void)out_size;
}

// round 8
// speedup vs baseline: 3.4322x; 1.1500x over previous
#include <cuda_runtime.h>
#include <cuda_fp16.h>
#include <math.h>

// Problem constants (fixed-shape problem)
#define BB 4
#define HH_ 180
#define WW 180
#define SPATIAL (HH_ * WW)       // 32400
#define C_L 128
#define C_C 128
#define CH_ALL 512
#define CH_HID 170
#define C_OUT 256

typedef unsigned int u32;
typedef unsigned long long u64;

// ---- fused kernel smem map (bytes) ----
// A/h (overlaid): [64m][256k] fp16, 512B rows, xor-swizzled : 0     .. 32767
// B buf0/buf1: [256n][64k] fp16 128B rows                    : 32768 .. 98303
#define SM_AH 0
#define SM_B  32768
#define SMEM_TOTAL 98304

// ---------------- device scratch ----------------------------------------------
__device__ __align__(16) float g_imgT[SPATIAL * C_C];     // img batch0 [pixel][chan]
__device__ unsigned g_keys[BB * CH_ALL];
__device__ __align__(16) float g_hid[2][BB][CH_HID];
__device__ __align__(16) float g_att_l[BB * C_L];
__device__ __align__(16) float g_att_c[BB * C_C];
// pre-swizzled fp16 weight images: 4 panels x 32KB ([256n][64k] 128B rows)
__device__ __align__(16) __half g_B1[65536];              // 128KB
__device__ __align__(16) __half g_B2[65536];

// ---------------- helpers -------------------------------------------------------
__device__ __forceinline__ u32 smem_u32(const void* p) {
    u32 r;
    asm("{ .reg .u64 t; cvta.to.shared.u64 t, %1; cvt.u32.u64 %0, t; }" : "=r"(r) : "l"(p));
    return r;
}
__device__ __forceinline__ void cp16(u32 dst, const void* src) {
    asm volatile("cp.async.cg.shared.global [%0], [%1], 16;" :: "r"(dst), "l"(src) : "memory");
}
__device__ __forceinline__ void cp_commit() { asm volatile("cp.async.commit_group;" ::: "memory"); }
__device__ __forceinline__ void cp_wait0()  { asm volatile("cp.async.wait_group 0;" ::: "memory"); }
__device__ __forceinline__ void cp_wait1()  { asm volatile("cp.async.wait_group 1;" ::: "memory"); }

__device__ __forceinline__ void ldsm4(u32 a, u32 &r0, u32 &r1, u32 &r2, u32 &r3) {
    asm volatile("ldmatrix.sync.aligned.m8n8.x4.shared.b16 {%0,%1,%2,%3}, [%4];"
                 : "=r"(r0), "=r"(r1), "=r"(r2), "=r"(r3) : "r"(a));
}
__device__ __forceinline__ void mma16816(float* c, const u32* a, u32 b0, u32 b1) {
    asm volatile("mma.sync.aligned.m16n8k16.row.col.f32.f16.f16.f32 "
                 "{%0,%1,%2,%3}, {%4,%5,%6,%7}, {%8,%9}, {%0,%1,%2,%3};"
                 : "+f"(c[0]), "+f"(c[1]), "+f"(c[2]), "+f"(c[3])
                 : "r"(a[0]), "r"(a[1]), "r"(a[2]), "r"(a[3]), "r"(b0), "r"(b1));
}

// Order-preserving float <-> uint encoding for atomic min/max
__device__ __forceinline__ unsigned enc_f(float x) {
    unsigned u = __float_as_uint(x);
    return (u & 0x80000000u) ? ~u : (u | 0x80000000u);
}
__device__ __forceinline__ float dec_f(unsigned k) {
    unsigned u = (k & 0x80000000u) ? (k ^ 0x80000000u) : ~k;
    return __uint_as_float(u);
}
__device__ __forceinline__ void min4(float4 &d, float4 v) {
    d.x = fminf(d.x, v.x); d.y = fminf(d.y, v.y);
    d.z = fminf(d.z, v.z); d.w = fminf(d.w, v.w);
}
__device__ __forceinline__ void max4(float4 &d, float4 v) {
    d.x = fmaxf(d.x, v.x); d.y = fmaxf(d.y, v.y);
    d.z = fmaxf(d.z, v.z); d.w = fmaxf(d.w, v.w);
}

// ---------------- kernel 0: init min/max keys -----------------------------------
__global__ void init_keys_kernel() {
    int i = blockIdx.x * blockDim.x + threadIdx.x;
    if (i >= BB * CH_ALL) return;
    int slot = i & (CH_ALL - 1);
    bool is_min = (slot < 128) || (slot >= 256 && slot < 384);
    g_keys[i] = is_min ? 0xFFFFFFFFu : 0x00000000u;
}

// ---------------- kernel 1: transpose img_bev[0] [C][P] -> [P][C] ---------------
__global__ void transpose_kernel(const float* __restrict__ img) {
    __shared__ float tile[32][33];
    int p0 = blockIdx.x * 32;
    int c0 = blockIdx.y * 32;
    int tx = threadIdx.x, ty = threadIdx.y;
#pragma unroll
    for (int j = 0; j < 4; ++j) {
        int c = c0 + ty + j * 8;
        int p = p0 + tx;
        if (p < SPATIAL) tile[ty + j * 8][tx] = img[c * SPATIAL + p];
    }
    __syncthreads();
#pragma unroll
    for (int j = 0; j < 4; ++j) {
        int p = p0 + ty + j * 8;
        int c = c0 + tx;
        if (p < SPATIAL) g_imgT[p * C_C + c] = tile[tx][ty + j * 8];
    }
}

// ---------------- kernel 1b: constant cam min/max for batches 1..3 --------------
// For b>=1: row = b*32400 + y*180 + x >= 32400 is ALWAYS clamped to 32398, so
// every voxel of those batches gathers pixel 32398 -> cmin = cmax = imgT[32398].
__global__ void const_cam_kernel() {
    int i = threadIdx.x;            // 0..383
    int b = 1 + (i >> 7);
    int c = i & 127;
    unsigned e = enc_f(g_imgT[(size_t)(SPATIAL - 2) * C_C + c]);
    atomicMin(&g_keys[b * CH_ALL + 256 + c], e);
    atomicMax(&g_keys[b * CH_ALL + 384 + c], e);
}

// ---------------- kernel 2: per-batch segment min/max ---------------------------
// 256-row chunks; uniform chunks vectorized (warp = row, 8 row-groups, smem
// tree reduce); cam loads skipped entirely for uniform b>=1 chunks (constant).
#define MM_CHUNK 256
__device__ __forceinline__ void flush_mm(int b, int c, float mn, float mx) {
    int msl, xsl;
    if (c < 128) { msl = c;             xsl = 128 + c; }
    else         { msl = 256 + c - 128; xsl = 384 + c - 128; }
    atomicMin(&g_keys[b * CH_ALL + msl], enc_f(mn));
    atomicMax(&g_keys[b * CH_ALL + xsl], enc_f(mx));
}
__global__ void __launch_bounds__(256) minmax_kernel(
    const float* __restrict__ lidar, const int* __restrict__ batch_idx,
    const int* __restrict__ y_idx, const int* __restrict__ x_idx, int N)
{
    __shared__ int sb[MM_CHUNK];
    __shared__ int sr[MM_CHUNK];
    __shared__ float red[4][8][128];
    int tid = threadIdx.x;
    int n0 = blockIdx.x * MM_CHUNK;
    int cnt = N - n0; if (cnt > MM_CHUNK) cnt = MM_CHUNK;
    if (cnt <= 0) return;
    if (tid < cnt) {
        int n = n0 + tid;
        int b = batch_idx[n];
        int r = b * SPATIAL + y_idx[n] * WW + x_idx[n];
        if (r > SPATIAL - 2) r = SPATIAL - 2;
        sb[tid] = b; sr[tid] = r;
    }
    __syncthreads();

    if (cnt == MM_CHUNK && sb[0] == sb[MM_CHUNK - 1]) {
        const int rg = tid >> 5;   // row-group 0..7
        const int c4 = tid & 31;   // float4 channel group
        const float4* lid4 = (const float4*)lidar;
        const bool do_cam = (sb[0] == 0);   // cam is constant for b>=1
        float4 mnl = make_float4( INFINITY,  INFINITY,  INFINITY,  INFINITY);
        float4 mxl = make_float4(-INFINITY, -INFINITY, -INFINITY, -INFINITY);
        float4 mnc = mnl, mxc = mxl;
        if (do_cam) {
            const float4* img4 = (const float4*)g_imgT;
#pragma unroll 4
            for (int i = 0; i < 32; ++i) {
                int row = i * 8 + rg;
                float4 lv = lid4[(size_t)(n0 + row) * 32 + c4];
                float4 cv = img4[(size_t)sr[row] * 32 + c4];
                min4(mnl, lv); max4(mxl, lv);
                min4(mnc, cv); max4(mxc, cv);
            }
        } else {
#pragma unroll 4
            for (int i = 0; i < 32; ++i) {
                int row = i * 8 + rg;
                float4 lv = lid4[(size_t)(n0 + row) * 32 + c4];
                min4(mnl, lv); max4(mxl, lv);
            }
        }
        int ch = c4 * 4;
        *(float4*)&red[0][rg][ch] = mnl;
        *(float4*)&red[1][rg][ch] = mxl;
        if (do_cam) {
            *(float4*)&red[2][rg][ch] = mnc;
            *(float4*)&red[3][rg][ch] = mxc;
        }
        __syncthreads();
        int c = tid;
        if (c < 128 || do_cam) {
            int qm = (c < 128) ? 0 : 2;
            int cc = c & 127;
            float mn = red[qm][0][cc], mx = red[qm + 1][0][cc];
#pragma unroll
            for (int g = 1; g < 8; ++g) {
                mn = fminf(mn, red[qm][g][cc]);
                mx = fmaxf(mx, red[qm + 1][g][cc]);
            }
            flush_mm(sb[0], c, mn, mx);
        }
    } else {
        // ---- boundary / tail chunk: scalar path ----
        const int c = tid;
        const bool cam = (c >= 128);
        const float* base = cam ? (g_imgT + (c - 128)) : (lidar + c);
        float mn = INFINITY, mx = -INFINITY;
        int cur = sb[0];
        for (int i = 0; i < cnt; ++i) {
            int b = sb[i];
            if (b != cur) { flush_mm(cur, c, mn, mx); cur = b; mn = INFINITY; mx = -INFINITY; }
            float v = cam ? base[(size_t)sr[i] * C_C] : base[(size_t)(n0 + i) * C_L];
            mn = fminf(mn, v); mx = fmaxf(mx, v);
        }
        flush_mm(cur, c, mn, mx);
    }
}

// ---------------- kernel 3a/3b: tiny gating MLPs --------------------------------
__global__ void __launch_bounds__(256) mlp1_kernel(
    const float* __restrict__ Wl1, const float* __restrict__ Wc1)
{
    int gw   = blockIdx.x * 8 + (threadIdx.x >> 5);
    int lane = threadIdx.x & 31;
    int net  = gw / (BB * CH_HID);
    int rem  = gw % (BB * CH_HID);
    int b    = rem / CH_HID;
    int j    = rem % CH_HID;
    const float* W = net ? Wc1 : Wl1;
    float s = 0.f;
#pragma unroll
    for (int t = 0; t < 16; ++t) {
        int k = lane + 32 * t;
        s = fmaf(dec_f(g_keys[b * CH_ALL + k]), W[k * CH_HID + j], s);
    }
#pragma unroll
    for (int o = 16; o; o >>= 1) s += __shfl_xor_sync(0xffffffffu, s, o);
    if (lane == 0) g_hid[net][b][j] = fmaxf(s, 0.f);
}
__global__ void __launch_bounds__(256) mlp2_kernel(
    const float* __restrict__ Wl2, const float* __restrict__ Wc2)
{
    int idx = blockIdx.x * 256 + threadIdx.x;
    int net = idx >> 9, rem = idx & 511;
    int b = rem >> 7, cc = rem & 127;
    const float* W2 = net ? Wc2 : Wl2;
    const float* h  = g_hid[net][b];
    float s = 0.f;
    for (int k = 0; k < CH_HID; ++k) s = fmaf(h[k], W2[k * 128 + cc], s);
    float v = fmaxf(s, 0.f);
    (net ? g_att_c : g_att_l)[b * 128 + cc] = 1.f / (1.f + expf(-v));
}

// ---------------- kernel 3c: weight prep (transpose + fp16 + pre-swizzle) -------
__global__ void __launch_bounds__(256) weight_prep_kernel(
    const float* __restrict__ Wf1, const float* __restrict__ Wf2)
{
    int idx = blockIdx.x * 256 + threadIdx.x;   // 2 * 65536
    int mat = idx >> 16;
    int rem = idx & 65535;
    int k = rem >> 8;          // 0..255 input dim
    int n = rem & 255;         // 0..255 output dim
    const float* W = mat ? Wf2 : Wf1;
    __half hv = __float2half_rn(W[k * 256 + n]);
    int p = k >> 6, k8l = (k >> 3) & 7, e = k & 7;
    u32 off = (u32)p * 32768u + (u32)n * 128u + ((u32)(k8l ^ (n & 7)) << 4) + (u32)e * 2u;
    __half* img = mat ? g_B2 : g_B1;
    *(unsigned short*)((char*)img + off) = *(unsigned short*)&hv;
}

// ---------------- fused GEMM stage (M=64, fp16 single-term) ------------------------
// acc += A x B, K=256 in 4 panels of 64, cp.async double-buffered.
// Warp tile 32m x 64n (8 warps: 2m x 4n).
__device__ __forceinline__ void gemm_stage(
    u32 smb, u32 Abase, const uint4* __restrict__ Bimg,
    float acc[2][8][4], int tid, int lane, int wm, int wn)
{
    const u32 Bb = smb + SM_B;
    // preload panel 0 -> buf0
    {
        u32 dst = Bb + (u32)tid * 16u;
        const uint4* s = Bimg + tid;
#pragma unroll
        for (int i = 0; i < 8; ++i) cp16(dst + i * 4096u, s + i * 256);
        cp_commit();
    }
#pragma unroll 1
    for (int p = 0; p < 4; ++p) {
        if (p < 3) {
            u32 dst = Bb + (u32)((p + 1) & 1) * 32768u + (u32)tid * 16u;
            const uint4* s = Bimg + (p + 1) * 2048 + tid;
#pragma unroll
            for (int i = 0; i < 8; ++i) cp16(dst + i * 4096u, s + i * 256);
            cp_commit();
            cp_wait1();
        } else {
            cp_wait0();
        }
        __syncthreads();
        u32 B = Bb + (u32)(p & 1) * 32768u;
#pragma unroll
        for (int s = 0; s < 4; ++s) {
            int k8 = p * 8 + s * 2 + (lane >> 4);    // A unit index 0..31
            int arow = wm + (lane & 15);
            u32 aoff = (u32)arow * 512u + ((u32)(k8 ^ (arow & 7)) << 4);
            // ---- A fragments: 2 m16 tiles ----
            u32 ah[2][4];
            ldsm4(Abase + aoff,          ah[0][0], ah[0][1], ah[0][2], ah[0][3]);
            ldsm4(Abase + aoff + 8192u,  ah[1][0], ah[1][1], ah[1][2], ah[1][3]);
            // ---- B fragments: 8 n8 ----
            int k8h = s * 2 + (lane >> 4);           // 0..7
            u32 bh[8][2];
#pragma unroll
            for (int j16 = 0; j16 < 4; ++j16) {
                int brow = wn + j16 * 16 + (lane & 15);
                u32 rb = B + (u32)brow * 128u;
                u32 r0, r1, r2, r3;
                ldsm4(rb + ((u32)(k8h ^ (brow & 7)) << 4), r0, r1, r2, r3);
                bh[2*j16][0] = r0;   bh[2*j16][1] = r2;
                bh[2*j16+1][0] = r1; bh[2*j16+1][1] = r3;
            }
#pragma unroll
            for (int t = 0; t < 2; ++t)
#pragma unroll
                for (int j = 0; j < 8; ++j)
                    mma16816(acc[t][j], ah[t], bh[j][0], bh[j][1]);
        }
        __syncthreads();
    }
}

// ---------------- kernel 4: fused gate + GEMM1 + ReLU + GEMM2 + ReLU -------------
__global__ void __launch_bounds__(256, 2) fused_mma_kernel(
    const float* __restrict__ lidar,
    const int* __restrict__ batch_idx,
    const int* __restrict__ y_idx,
    const int* __restrict__ x_idx,
    float* __restrict__ out, int N)
{
    extern __shared__ char sm[];
    const u32 smb = smem_u32(sm);
    const int tid  = threadIdx.x;
    const int lane = tid & 31;
    const int wid  = tid >> 5;
    const int wm   = (wid & 1) * 32;
    const int wn   = (wid >> 1) * 64;

    // ---- phase 1: gather + gate + fp16 cvt into A smem (swizzled) ----
    {
        int m = tid >> 2, q = tid & 3;          // 4 threads per row, 64 ch each
        int n = blockIdx.x * 64 + m;
        int nn = n < N ? n : N - 1;
        int b = batch_idx[nn];
        const float* src;
        const float* att;
        if (q < 2) { src = lidar + (size_t)nn * C_L; att = g_att_l + b * 128; }
        else {
            int r = b * SPATIAL + y_idx[nn] * WW + x_idx[nn];
            if (r > SPATIAL - 2) r = SPATIAL - 2;
            src = g_imgT + (size_t)r * C_C; att = g_att_c + b * 128;
        }
        const float4* s4 = (const float4*)src;
        const float4* g4 = (const float4*)att;
        int ho = (q & 1) * 16;                   // float4 offset within source
        u32 rowb = (u32)m * 512u;
        u32 xm = (u32)(m & 7);
#pragma unroll
        for (int i = 0; i < 8; ++i) {
            float4 a0 = s4[ho + 2*i], a1 = s4[ho + 2*i + 1];
            float4 q0 = g4[ho + 2*i], q1 = g4[ho + 2*i + 1];
            __half2 h0 = __floats2half2_rn(a0.x*q0.x, a0.y*q0.y);
            __half2 h1 = __floats2half2_rn(a0.z*q0.z, a0.w*q0.w);
            __half2 h2 = __floats2half2_rn(a1.x*q1.x, a1.y*q1.y);
            __half2 h3 = __floats2half2_rn(a1.z*q1.z, a1.w*q1.w);
            uint4 H = make_uint4(*(u32*)&h0, *(u32*)&h1, *(u32*)&h2, *(u32*)&h3);
            u32 k8 = (u32)(q * 8 + i);          // 0..31
            u32 off = rowb + ((k8 ^ xm) << 4);
            *(uint4*)(sm + SM_AH + off) = H;
        }
    }
    // (first __syncthreads inside gemm_stage covers A writes)

    float acc[2][8][4];
#pragma unroll
    for (int t = 0; t < 2; ++t)
#pragma unroll
        for (int j = 0; j < 8; ++j)
#pragma unroll
            for (int c = 0; c < 4; ++c) acc[t][j][c] = 0.f;

    // ---- GEMM1 ----
    gemm_stage(smb, smb + SM_AH, (const uint4*)g_B1, acc, tid, lane, wm, wn);

    // ---- epilogue 1: relu + fp16 cvt -> h (overwrites A smem; GEMM1's trailing
    //      __syncthreads guarantees all A reads are complete) ----
    {
#pragma unroll
        for (int t = 0; t < 2; ++t) {
            int r0 = wm + 16 * t + (lane >> 2);
            int r1 = r0 + 8;
#pragma unroll
            for (int j = 0; j < 8; ++j) {
                float* c = acc[t][j];
                u32 k8 = (u32)((wn >> 3) + j);
                u32 eb = (u32)(lane & 3) * 4u;
                __half2 p0 = __floats2half2_rn(fmaxf(c[0], 0.f), fmaxf(c[1], 0.f));
                __half2 p1 = __floats2half2_rn(fmaxf(c[2], 0.f), fmaxf(c[3], 0.f));
                u32 o0 = (u32)r0 * 512u + ((k8 ^ (u32)(r0 & 7)) << 4) + eb;
                u32 o1 = (u32)r1 * 512u + ((k8 ^ (u32)(r1 & 7)) << 4) + eb;
                *(u32*)(sm + SM_AH + o0) = *(u32*)&p0;
                *(u32*)(sm + SM_AH + o1) = *(u32*)&p1;
            }
        }
    }
    __syncthreads();

#pragma unroll
    for (int t = 0; t < 2; ++t)
#pragma unroll
        for (int j = 0; j < 8; ++j)
#pragma unroll
            for (int c = 0; c < 4; ++c) acc[t][j][c] = 0.f;

    // ---- GEMM2 ----
    gemm_stage(smb, smb + SM_AH, (const uint4*)g_B2, acc, tid, lane, wm, wn);

    // ---- epilogue 2: relu -> gmem ----
    {
        int mbase = blockIdx.x * 64;
#pragma unroll
        for (int t = 0; t < 2; ++t) {
            int r0 = mbase + wm + 16 * t + (lane >> 2);
            int r1 = r0 + 8;
#pragma unroll
            for (int j = 0; j < 8; ++j) {
                float* c = acc[t][j];
                int col = wn + 8 * j + 2 * (lane & 3);
                if (r0 < N) {
                    float2 v = make_float2(fmaxf(c[0], 0.f), fmaxf(c[1], 0.f));
                    *(float2*)(out + (size_t)r0 * 256 + col) = v;
                }
                if (r1 < N) {
                    float2 v = make_float2(fmaxf(c[2], 0.f), fmaxf(c[3], 0.f));
                    *(float2*)(out + (size_t)r1 * 256 + col) = v;
                }
            }
        }
    }
}

// ---------------- host launcher ---------------------------------------------------
extern "C" void kernel_launch(void* const* d_in, const int* in_sizes, int n_in,
                              void* d_out, int out_size)
{
    int iL = -1, iImg = -1, iB = -1, iY = -1, iX = -1;
    int iWl1 = -1, iWl2 = -1, iWc1 = -1, iWc2 = -1, iWf1 = -1, iWf2 = -1;
    for (int i = 0; i < n_in; ++i) {
        int s = in_sizes[i];
        if      (s == BB * C_C * SPATIAL)      iImg = i;
        else if (s == CH_ALL * CH_HID)         { if (iWl1 < 0) iWl1 = i; else iWc1 = i; }
        else if (s == CH_HID * C_L)            { if (iWl2 < 0) iWl2 = i; else iWc2 = i; }
        else if (s == C_OUT * C_OUT)           { if (iWf1 < 0) iWf1 = i; else iWf2 = i; }
        else if (s % C_L == 0 && s >= 1000000) iL = i;
        else                                   { if (iB < 0) iB = i; else if (iY < 0) iY = i; else iX = i; }
    }
    const float* lidar = (const float*)d_in[iL];
    const float* img   = (const float*)d_in[iImg];
    const int*   bidx  = (const int*)d_in[iB];
    const int*   yidx  = (const int*)d_in[iY];
    const int*   xidx  = (const int*)d_in[iX];
    const float* Wl1   = (const float*)d_in[iWl1];
    const float* Wl2   = (const float*)d_in[iWl2];
    const float* Wc1   = (const float*)d_in[iWc1];
    const float* Wc2   = (const float*)d_in[iWc2];
    const float* Wf1   = (const float*)d_in[iWf1];
    const float* Wf2   = (const float*)d_in[iWf2];
    float* out = (float*)d_out;
    const int N = in_sizes[iL] / C_L;

    cudaFuncSetAttribute(fused_mma_kernel, cudaFuncAttributeMaxDynamicSharedMemorySize, SMEM_TOTAL);

    init_keys_kernel<<<(BB * CH_ALL + 255) / 256, 256>>>();
    transpose_kernel<<<dim3((SPATIAL + 31) / 32, C_C / 32), dim3(32, 8)>>>(img);
    const_cam_kernel<<<1, 384>>>();
    weight_prep_kernel<<<512, 256>>>(Wf1, Wf2);
    minmax_kernel<<<(N + MM_CHUNK - 1) / MM_CHUNK, 256>>>(lidar, bidx, yidx, xidx, N);
    mlp1_kernel<<<CH_HID, 256>>>(Wl1, Wc1);
    mlp2_kernel<<<4, 256>>>(Wl2, Wc2);
    fused_mma_kernel<<<(N + 63) / 64, 256, SMEM_TOTAL>>>(lidar, bidx, yidx, xidx, out, N);
    (void)out_size;
}

// round 9
// speedup vs baseline: 3.6473x; 1.0626x over previous
#include <cuda_runtime.h>
#include <cuda_fp16.h>
#include <math.h>

// Problem constants (fixed-shape problem)
#define BB 4
#define HH_ 180
#define WW 180
#define SPATIAL (HH_ * WW)       // 32400
#define C_L 128
#define C_C 128
#define CH_ALL 512
#define CH_HID 170
#define C_OUT 256

typedef unsigned int u32;
typedef unsigned long long u64;

// ---- fused kernel smem map (bytes) ----
// A/h (overlaid): [64m][256k] fp16, 512B rows, xor-swizzled : 0     .. 32767
// B buf0/buf1: [256n][64k] fp16 128B rows                    : 32768 .. 98303
// sb: per-row batch ids                                       : 98304 .. 98559
#define SM_AH 0
#define SM_B  32768
#define SM_SB 98304
#define SMEM_TOTAL 98560

// ---------------- device scratch ----------------------------------------------
__device__ __align__(16) float g_imgT[SPATIAL * C_C];     // img batch0 [pixel][chan]
__device__ unsigned g_keys[BB * CH_ALL];
__device__ __align__(16) float g_hid[2][BB][CH_HID];
__device__ __align__(16) float g_att_l[BB * C_L];
__device__ __align__(16) float g_att_c[BB * C_C];
__device__ __align__(16) float g_hc[BB * C_OUT];          // per-batch GEMM1 cam bias
// pre-swizzled fp16 weight images: 4 panels x 32KB ([256n][64k] 128B rows)
__device__ __align__(16) __half g_B1[65536];              // 128KB
__device__ __align__(16) __half g_B2[65536];

// ---------------- helpers -------------------------------------------------------
__device__ __forceinline__ u32 smem_u32(const void* p) {
    u32 r;
    asm("{ .reg .u64 t; cvta.to.shared.u64 t, %1; cvt.u32.u64 %0, t; }" : "=r"(r) : "l"(p));
    return r;
}
__device__ __forceinline__ void cp16(u32 dst, const void* src) {
    asm volatile("cp.async.cg.shared.global [%0], [%1], 16;" :: "r"(dst), "l"(src) : "memory");
}
__device__ __forceinline__ void cp_commit() { asm volatile("cp.async.commit_group;" ::: "memory"); }
__device__ __forceinline__ void cp_wait0()  { asm volatile("cp.async.wait_group 0;" ::: "memory"); }
__device__ __forceinline__ void cp_wait1()  { asm volatile("cp.async.wait_group 1;" ::: "memory"); }

__device__ __forceinline__ void ldsm4(u32 a, u32 &r0, u32 &r1, u32 &r2, u32 &r3) {
    asm volatile("ldmatrix.sync.aligned.m8n8.x4.shared.b16 {%0,%1,%2,%3}, [%4];"
                 : "=r"(r0), "=r"(r1), "=r"(r2), "=r"(r3) : "r"(a));
}
__device__ __forceinline__ void mma16816(float* c, const u32* a, u32 b0, u32 b1) {
    asm volatile("mma.sync.aligned.m16n8k16.row.col.f32.f16.f16.f32 "
                 "{%0,%1,%2,%3}, {%4,%5,%6,%7}, {%8,%9}, {%0,%1,%2,%3};"
                 : "+f"(c[0]), "+f"(c[1]), "+f"(c[2]), "+f"(c[3])
                 : "r"(a[0]), "r"(a[1]), "r"(a[2]), "r"(a[3]), "r"(b0), "r"(b1));
}

// Order-preserving float <-> uint encoding for atomic min/max
__device__ __forceinline__ unsigned enc_f(float x) {
    unsigned u = __float_as_uint(x);
    return (u & 0x80000000u) ? ~u : (u | 0x80000000u);
}
__device__ __forceinline__ float dec_f(unsigned k) {
    unsigned u = (k & 0x80000000u) ? (k ^ 0x80000000u) : ~k;
    return __uint_as_float(u);
}
__device__ __forceinline__ void min4(float4 &d, float4 v) {
    d.x = fminf(d.x, v.x); d.y = fminf(d.y, v.y);
    d.z = fminf(d.z, v.z); d.w = fminf(d.w, v.w);
}
__device__ __forceinline__ void max4(float4 &d, float4 v) {
    d.x = fmaxf(d.x, v.x); d.y = fmaxf(d.y, v.y);
    d.z = fmaxf(d.z, v.z); d.w = fmaxf(d.w, v.w);
}

// ---------------- kernel 0: init min/max keys -----------------------------------
__global__ void init_keys_kernel() {
    int i = blockIdx.x * blockDim.x + threadIdx.x;
    if (i >= BB * CH_ALL) return;
    int slot = i & (CH_ALL - 1);
    bool is_min = (slot < 128) || (slot >= 256 && slot < 384);
    g_keys[i] = is_min ? 0xFFFFFFFFu : 0x00000000u;
}

// ---------------- kernel 1: transpose img_bev[0] [C][P] -> [P][C] ---------------
__global__ void transpose_kernel(const float* __restrict__ img) {
    __shared__ float tile[32][33];
    int p0 = blockIdx.x * 32;
    int c0 = blockIdx.y * 32;
    int tx = threadIdx.x, ty = threadIdx.y;
#pragma unroll
    for (int j = 0; j < 4; ++j) {
        int c = c0 + ty + j * 8;
        int p = p0 + tx;
        if (p < SPATIAL) tile[ty + j * 8][tx] = img[c * SPATIAL + p];
    }
    __syncthreads();
#pragma unroll
    for (int j = 0; j < 4; ++j) {
        int p = p0 + ty + j * 8;
        int c = c0 + tx;
        if (p < SPATIAL) g_imgT[p * C_C + c] = tile[tx][ty + j * 8];
    }
}

// ---------------- kernel 1b: constant cam min/max for batches 1..3 --------------
// For b>=1: row = b*32400 + y*180 + x >= 32400 is ALWAYS clamped to 32398, so
// every voxel of those batches gathers pixel 32398 -> cmin = cmax = imgT[32398].
__global__ void const_cam_kernel() {
    int i = threadIdx.x;            // 0..383
    int b = 1 + (i >> 7);
    int c = i & 127;
    unsigned e = enc_f(g_imgT[(size_t)(SPATIAL - 2) * C_C + c]);
    atomicMin(&g_keys[b * CH_ALL + 256 + c], e);
    atomicMax(&g_keys[b * CH_ALL + 384 + c], e);
}

// ---------------- kernel 2: per-batch segment min/max ---------------------------
#define MM_CHUNK 256
__device__ __forceinline__ void flush_mm(int b, int c, float mn, float mx) {
    int msl, xsl;
    if (c < 128) { msl = c;             xsl = 128 + c; }
    else         { msl = 256 + c - 128; xsl = 384 + c - 128; }
    atomicMin(&g_keys[b * CH_ALL + msl], enc_f(mn));
    atomicMax(&g_keys[b * CH_ALL + xsl], enc_f(mx));
}
__global__ void __launch_bounds__(256) minmax_kernel(
    const float* __restrict__ lidar, const int* __restrict__ batch_idx,
    const int* __restrict__ y_idx, const int* __restrict__ x_idx, int N)
{
    __shared__ int sb[MM_CHUNK];
    __shared__ int sr[MM_CHUNK];
    __shared__ float red[4][8][128];
    int tid = threadIdx.x;
    int n0 = blockIdx.x * MM_CHUNK;
    int cnt = N - n0; if (cnt > MM_CHUNK) cnt = MM_CHUNK;
    if (cnt <= 0) return;
    if (tid < cnt) {
        int n = n0 + tid;
        int b = batch_idx[n];
        int r = b * SPATIAL + y_idx[n] * WW + x_idx[n];
        if (r > SPATIAL - 2) r = SPATIAL - 2;
        sb[tid] = b; sr[tid] = r;
    }
    __syncthreads();

    if (cnt == MM_CHUNK && sb[0] == sb[MM_CHUNK - 1]) {
        const int rg = tid >> 5;
        const int c4 = tid & 31;
        const float4* lid4 = (const float4*)lidar;
        const bool do_cam = (sb[0] == 0);   // cam is constant for b>=1
        float4 mnl = make_float4( INFINITY,  INFINITY,  INFINITY,  INFINITY);
        float4 mxl = make_float4(-INFINITY, -INFINITY, -INFINITY, -INFINITY);
        float4 mnc = mnl, mxc = mxl;
        if (do_cam) {
            const float4* img4 = (const float4*)g_imgT;
#pragma unroll 4
            for (int i = 0; i < 32; ++i) {
                int row = i * 8 + rg;
                float4 lv = lid4[(size_t)(n0 + row) * 32 + c4];
                float4 cv = img4[(size_t)sr[row] * 32 + c4];
                min4(mnl, lv); max4(mxl, lv);
                min4(mnc, cv); max4(mxc, cv);
            }
        } else {
#pragma unroll 4
            for (int i = 0; i < 32; ++i) {
                int row = i * 8 + rg;
                float4 lv = lid4[(size_t)(n0 + row) * 32 + c4];
                min4(mnl, lv); max4(mxl, lv);
            }
        }
        int ch = c4 * 4;
        *(float4*)&red[0][rg][ch] = mnl;
        *(float4*)&red[1][rg][ch] = mxl;
        if (do_cam) {
            *(float4*)&red[2][rg][ch] = mnc;
            *(float4*)&red[3][rg][ch] = mxc;
        }
        __syncthreads();
        int c = tid;
        if (c < 128 || do_cam) {
            int qm = (c < 128) ? 0 : 2;
            int cc = c & 127;
            float mn = red[qm][0][cc], mx = red[qm + 1][0][cc];
#pragma unroll
            for (int g = 1; g < 8; ++g) {
                mn = fminf(mn, red[qm][g][cc]);
                mx = fmaxf(mx, red[qm + 1][g][cc]);
            }
            flush_mm(sb[0], c, mn, mx);
        }
    } else {
        const int c = tid;
        const bool cam = (c >= 128);
        const float* base = cam ? (g_imgT + (c - 128)) : (lidar + c);
        float mn = INFINITY, mx = -INFINITY;
        int cur = sb[0];
        for (int i = 0; i < cnt; ++i) {
            int b = sb[i];
            if (b != cur) { flush_mm(cur, c, mn, mx); cur = b; mn = INFINITY; mx = -INFINITY; }
            float v = cam ? base[(size_t)sr[i] * C_C] : base[(size_t)(n0 + i) * C_L];
            mn = fminf(mn, v); mx = fmaxf(mx, v);
        }
        flush_mm(cur, c, mn, mx);
    }
}

// ---------------- kernel 3a/3b: tiny gating MLPs --------------------------------
__global__ void __launch_bounds__(256) mlp1_kernel(
    const float* __restrict__ Wl1, const float* __restrict__ Wc1)
{
    int gw   = blockIdx.x * 8 + (threadIdx.x >> 5);
    int lane = threadIdx.x & 31;
    int net  = gw / (BB * CH_HID);
    int rem  = gw % (BB * CH_HID);
    int b    = rem / CH_HID;
    int j    = rem % CH_HID;
    const float* W = net ? Wc1 : Wl1;
    float s = 0.f;
#pragma unroll
    for (int t = 0; t < 16; ++t) {
        int k = lane + 32 * t;
        s = fmaf(dec_f(g_keys[b * CH_ALL + k]), W[k * CH_HID + j], s);
    }
#pragma unroll
    for (int o = 16; o; o >>= 1) s += __shfl_xor_sync(0xffffffffu, s, o);
    if (lane == 0) g_hid[net][b][j] = fmaxf(s, 0.f);
}
__global__ void __launch_bounds__(256) mlp2_kernel(
    const float* __restrict__ Wl2, const float* __restrict__ Wc2)
{
    int idx = blockIdx.x * 256 + threadIdx.x;
    int net = idx >> 9, rem = idx & 511;
    int b = rem >> 7, cc = rem & 127;
    const float* W2 = net ? Wc2 : Wl2;
    const float* h  = g_hid[net][b];
    float s = 0.f;
    for (int k = 0; k < CH_HID; ++k) s = fmaf(h[k], W2[k * 128 + cc], s);
    float v = fmaxf(s, 0.f);
    (net ? g_att_c : g_att_l)[b * 128 + cc] = 1.f / (1.f + expf(-v));
}

// ---------------- kernel 3d: per-batch GEMM1 cam bias (fp32) --------------------
// hc[b][n] = sum_k (att_c[b][k] * imgT[32398][k]) * Wf1[128+k][n]
__global__ void __launch_bounds__(256) hc_kernel(const float* __restrict__ Wf1) {
    __shared__ float gc[128];
    int b = blockIdx.x, t = threadIdx.x;
    if (t < 128) gc[t] = g_att_c[b * 128 + t] * g_imgT[(size_t)(SPATIAL - 2) * C_C + t];
    __syncthreads();
    float s = 0.f;
#pragma unroll 4
    for (int k = 0; k < 128; ++k)
        s = fmaf(gc[k], Wf1[(128 + k) * 256 + t], s);
    g_hc[b * 256 + t] = s;
}

// ---------------- kernel 3c: weight prep (transpose + fp16 + pre-swizzle) -------
__global__ void __launch_bounds__(256) weight_prep_kernel(
    const float* __restrict__ Wf1, const float* __restrict__ Wf2)
{
    int idx = blockIdx.x * 256 + threadIdx.x;   // 2 * 65536
    int mat = idx >> 16;
    int rem = idx & 65535;
    int k = rem >> 8;          // 0..255 input dim
    int n = rem & 255;         // 0..255 output dim
    const float* W = mat ? Wf2 : Wf1;
    __half hv = __float2half_rn(W[k * 256 + n]);
    int p = k >> 6, k8l = (k >> 3) & 7, e = k & 7;
    u32 off = (u32)p * 32768u + (u32)n * 128u + ((u32)(k8l ^ (n & 7)) << 4) + (u32)e * 2u;
    __half* img = mat ? g_B2 : g_B1;
    *(unsigned short*)((char*)img + off) = *(unsigned short*)&hv;
}

// ---------------- fused GEMM stage (M=64, fp16 single-term, NP panels) -----------
template<int NP>
__device__ __forceinline__ void gemm_stage(
    u32 smb, u32 Abase, const uint4* __restrict__ Bimg,
    float acc[2][8][4], int tid, int lane, int wm, int wn)
{
    const u32 Bb = smb + SM_B;
    {
        u32 dst = Bb + (u32)tid * 16u;
        const uint4* s = Bimg + tid;
#pragma unroll
        for (int i = 0; i < 8; ++i) cp16(dst + i * 4096u, s + i * 256);
        cp_commit();
    }
#pragma unroll 1
    for (int p = 0; p < NP; ++p) {
        if (p < NP - 1) {
            u32 dst = Bb + (u32)((p + 1) & 1) * 32768u + (u32)tid * 16u;
            const uint4* s = Bimg + (p + 1) * 2048 + tid;
#pragma unroll
            for (int i = 0; i < 8; ++i) cp16(dst + i * 4096u, s + i * 256);
            cp_commit();
            cp_wait1();
        } else {
            cp_wait0();
        }
        __syncthreads();
        u32 B = Bb + (u32)(p & 1) * 32768u;
#pragma unroll
        for (int s = 0; s < 4; ++s) {
            int k8 = p * 8 + s * 2 + (lane >> 4);    // A unit index
            int arow = wm + (lane & 15);
            u32 aoff = (u32)arow * 512u + ((u32)(k8 ^ (arow & 7)) << 4);
            u32 ah[2][4];
            ldsm4(Abase + aoff,          ah[0][0], ah[0][1], ah[0][2], ah[0][3]);
            ldsm4(Abase + aoff + 8192u,  ah[1][0], ah[1][1], ah[1][2], ah[1][3]);
            int k8h = s * 2 + (lane >> 4);
            u32 bh[8][2];
#pragma unroll
            for (int j16 = 0; j16 < 4; ++j16) {
                int brow = wn + j16 * 16 + (lane & 15);
                u32 rb = B + (u32)brow * 128u;
                u32 r0, r1, r2, r3;
                ldsm4(rb + ((u32)(k8h ^ (brow & 7)) << 4), r0, r1, r2, r3);
                bh[2*j16][0] = r0;   bh[2*j16][1] = r2;
                bh[2*j16+1][0] = r1; bh[2*j16+1][1] = r3;
            }
#pragma unroll
            for (int t = 0; t < 2; ++t)
#pragma unroll
                for (int j = 0; j < 8; ++j)
                    mma16816(acc[t][j], ah[t], bh[j][0], bh[j][1]);
        }
        __syncthreads();
    }
}

// ---------------- kernel 4: fused gate + GEMM1 + ReLU + GEMM2 + ReLU -------------
__global__ void __launch_bounds__(256, 2) fused_mma_kernel(
    const float* __restrict__ lidar,
    const int* __restrict__ batch_idx,
    const int* __restrict__ y_idx,
    const int* __restrict__ x_idx,
    float* __restrict__ out, int N)
{
    extern __shared__ char sm[];
    const u32 smb = smem_u32(sm);
    int* sbv = (int*)(sm + SM_SB);
    const int tid  = threadIdx.x;
    const int lane = tid & 31;
    const int wid  = tid >> 5;
    const int wm   = (wid & 1) * 32;
    const int wn   = (wid >> 1) * 64;

    // tile is "short" (cam half constant -> K=128 GEMM1 + bias) iff first row b>=1
    int first_n = blockIdx.x * 64;
    if (first_n >= N) first_n = N - 1;
    const bool short_tile = (batch_idx[first_n] >= 1);

    // ---- phase 1: gather + gate + fp16 cvt into A smem (swizzled) ----
    {
        int m = tid >> 2, q = tid & 3;          // 4 threads per row, 64 ch each
        int n = blockIdx.x * 64 + m;
        int nn = n < N ? n : N - 1;
        int b = batch_idx[nn];
        if (q == 0) sbv[m] = b;
        if (!(short_tile && q >= 2)) {          // skip cam gather on short tiles
            const float* src;
            const float* att;
            if (q < 2) { src = lidar + (size_t)nn * C_L; att = g_att_l + b * 128; }
            else {
                int r = b * SPATIAL + y_idx[nn] * WW + x_idx[nn];
                if (r > SPATIAL - 2) r = SPATIAL - 2;
                src = g_imgT + (size_t)r * C_C; att = g_att_c + b * 128;
            }
            const float4* s4 = (const float4*)src;
            const float4* g4 = (const float4*)att;
            int ho = (q & 1) * 16;
            u32 rowb = (u32)m * 512u;
            u32 xm = (u32)(m & 7);
#pragma unroll
            for (int i = 0; i < 8; ++i) {
                float4 a0 = s4[ho + 2*i], a1 = s4[ho + 2*i + 1];
                float4 q0 = g4[ho + 2*i], q1 = g4[ho + 2*i + 1];
                __half2 h0 = __floats2half2_rn(a0.x*q0.x, a0.y*q0.y);
                __half2 h1 = __floats2half2_rn(a0.z*q0.z, a0.w*q0.w);
                __half2 h2 = __floats2half2_rn(a1.x*q1.x, a1.y*q1.y);
                __half2 h3 = __floats2half2_rn(a1.z*q1.z, a1.w*q1.w);
                uint4 H = make_uint4(*(u32*)&h0, *(u32*)&h1, *(u32*)&h2, *(u32*)&h3);
                u32 k8 = (u32)(q * 8 + i);
                u32 off = rowb + ((k8 ^ xm) << 4);
                *(uint4*)(sm + SM_AH + off) = H;
            }
        }
    }
    __syncthreads();   // sbv + A visible

    // ---- acc init: zero (full) or per-row cam bias hc[b] (short) ----
    float acc[2][8][4];
    if (short_tile) {
#pragma unroll
        for (int t = 0; t < 2; ++t) {
            int r0 = wm + 16 * t + (lane >> 2);
            int r1 = r0 + 8;
            const float* h0 = g_hc + sbv[r0] * 256;
            const float* h1 = g_hc + sbv[r1] * 256;
#pragma unroll
            for (int j = 0; j < 8; ++j) {
                int col = wn + 8 * j + 2 * (lane & 3);
                acc[t][j][0] = h0[col];   acc[t][j][1] = h0[col + 1];
                acc[t][j][2] = h1[col];   acc[t][j][3] = h1[col + 1];
            }
        }
    } else {
#pragma unroll
        for (int t = 0; t < 2; ++t)
#pragma unroll
            for (int j = 0; j < 8; ++j)
#pragma unroll
                for (int c = 0; c < 4; ++c) acc[t][j][c] = 0.f;
    }

    // ---- GEMM1: K=128 (short) or K=256 (full) ----
    if (short_tile)
        gemm_stage<2>(smb, smb + SM_AH, (const uint4*)g_B1, acc, tid, lane, wm, wn);
    else
        gemm_stage<4>(smb, smb + SM_AH, (const uint4*)g_B1, acc, tid, lane, wm, wn);

    // ---- epilogue 1: relu + fp16 cvt -> h (overwrites A smem; GEMM1's trailing
    //      __syncthreads guarantees all A reads are complete) ----
    {
#pragma unroll
        for (int t = 0; t < 2; ++t) {
            int r0 = wm + 16 * t + (lane >> 2);
            int r1 = r0 + 8;
#pragma unroll
            for (int j = 0; j < 8; ++j) {
                float* c = acc[t][j];
                u32 k8 = (u32)((wn >> 3) + j);
                u32 eb = (u32)(lane & 3) * 4u;
                __half2 p0 = __floats2half2_rn(fmaxf(c[0], 0.f), fmaxf(c[1], 0.f));
                __half2 p1 = __floats2half2_rn(fmaxf(c[2], 0.f), fmaxf(c[3], 0.f));
                u32 o0 = (u32)r0 * 512u + ((k8 ^ (u32)(r0 & 7)) << 4) + eb;
                u32 o1 = (u32)r1 * 512u + ((k8 ^ (u32)(r1 & 7)) << 4) + eb;
                *(u32*)(sm + SM_AH + o0) = *(u32*)&p0;
                *(u32*)(sm + SM_AH + o1) = *(u32*)&p1;
            }
        }
    }
    __syncthreads();

#pragma unroll
    for (int t = 0; t < 2; ++t)
#pragma unroll
        for (int j = 0; j < 8; ++j)
#pragma unroll
            for (int c = 0; c < 4; ++c) acc[t][j][c] = 0.f;

    // ---- GEMM2 ----
    gemm_stage<4>(smb, smb + SM_AH, (const uint4*)g_B2, acc, tid, lane, wm, wn);

    // ---- epilogue 2: relu -> gmem ----
    {
        int mbase = blockIdx.x * 64;
#pragma unroll
        for (int t = 0; t < 2; ++t) {
            int r0 = mbase + wm + 16 * t + (lane >> 2);
            int r1 = r0 + 8;
#pragma unroll
            for (int j = 0; j < 8; ++j) {
                float* c = acc[t][j];
                int col = wn + 8 * j + 2 * (lane & 3);
                if (r0 < N) {
                    float2 v = make_float2(fmaxf(c[0], 0.f), fmaxf(c[1], 0.f));
                    *(float2*)(out + (size_t)r0 * 256 + col) = v;
                }
                if (r1 < N) {
                    float2 v = make_float2(fmaxf(c[2], 0.f), fmaxf(c[3], 0.f));
                    *(float2*)(out + (size_t)r1 * 256 + col) = v;
                }
            }
        }
    }
}

// ---------------- host launcher ---------------------------------------------------
extern "C" void kernel_launch(void* const* d_in, const int* in_sizes, int n_in,
                              void* d_out, int out_size)
{
    int iL = -1, iImg = -1, iB = -1, iY = -1, iX = -1;
    int iWl1 = -1, iWl2 = -1, iWc1 = -1, iWc2 = -1, iWf1 = -1, iWf2 = -1;
    for (int i = 0; i < n_in; ++i) {
        int s = in_sizes[i];
        if      (s == BB * C_C * SPATIAL)      iImg = i;
        else if (s == CH_ALL * CH_HID)         { if (iWl1 < 0) iWl1 = i; else iWc1 = i; }
        else if (s == CH_HID * C_L)            { if (iWl2 < 0) iWl2 = i; else iWc2 = i; }
        else if (s == C_OUT * C_OUT)           { if (iWf1 < 0) iWf1 = i; else iWf2 = i; }
        else if (s % C_L == 0 && s >= 1000000) iL = i;
        else                                   { if (iB < 0) iB = i; else if (iY < 0) iY = i; else iX = i; }
    }
    const float* lidar = (const float*)d_in[iL];
    const float* img   = (const float*)d_in[iImg];
    const int*   bidx  = (const int*)d_in[iB];
    const int*   yidx  = (const int*)d_in[iY];
    const int*   xidx  = (const int*)d_in[iX];
    const float* Wl1   = (const float*)d_in[iWl1];
    const float* Wl2   = (const float*)d_in[iWl2];
    const float* Wc1   = (const float*)d_in[iWc1];
    const float* Wc2   = (const float*)d_in[iWc2];
    const float* Wf1   = (const float*)d_in[iWf1];
    const float* Wf2   = (const float*)d_in[iWf2];
    float* out = (float*)d_out;
    const int N = in_sizes[iL] / C_L;

    cudaFuncSetAttribute(fused_mma_kernel, cudaFuncAttributeMaxDynamicSharedMemorySize, SMEM_TOTAL);

    init_keys_kernel<<<(BB * CH_ALL + 255) / 256, 256>>>();
    transpose_kernel<<<dim3((SPATIAL + 31) / 32, C_C / 32), dim3(32, 8)>>>(img);
    const_cam_kernel<<<1, 384>>>();
    weight_prep_kernel<<<512, 256>>>(Wf1, Wf2);
    minmax_kernel<<<(N + MM_CHUNK - 1) / MM_CHUNK, 256>>>(lidar, bidx, yidx, xidx, N);
    mlp1_kernel<<<CH_HID, 256>>>(Wl1, Wc1);
    mlp2_kernel<<<4, 256>>>(Wl2, Wc2);
    hc_kernel<<<BB, 256>>>(Wf1);
    fused_mma_kernel<<<(N + 63) / 64, 256, SMEM_TOTAL>>>(lidar, bidx, yidx, xidx, out, N);
    (void)out_size;
}

// round 10
// speedup vs baseline: 4.0052x; 1.0982x over previous
#include <cuda_runtime.h>
#include <cuda_fp16.h>
#include <math.h>

// Problem constants (fixed-shape problem)
#define BB 4
#define HH_ 180
#define WW 180
#define SPATIAL (HH_ * WW)       // 32400
#define C_L 128
#define C_C 128
#define CH_ALL 512
#define CH_HID 170
#define C_OUT 256

typedef unsigned int u32;
typedef unsigned long long u64;

// ---- fused kernel smem map (bytes) ----
// A/h (overlaid): [64m][256k] fp16, 512B rows, xor-swizzled : 0     .. 32767
// B buf0/buf1: [256n][64k] fp16 128B rows                    : 32768 .. 98303
// sb: per-row batch ids                                       : 98304 .. 98559
#define SM_AH 0
#define SM_B  32768
#define SM_SB 98304
#define SMEM_TOTAL 98560

// ---------------- device scratch ----------------------------------------------
__device__ __align__(16) float g_imgT[SPATIAL * C_C];     // img batch0 [pixel][chan]
__device__ unsigned g_keys[BB * CH_ALL];
__device__ __align__(16) float g_hid[2][BB][CH_HID];
__device__ __align__(16) float g_att_l[BB * C_L];
__device__ __align__(16) float g_att_c[BB * C_C];
__device__ __align__(16) float g_hc[BB * C_OUT];          // per-batch GEMM1 cam bias
// pre-swizzled fp16 weight images: 4 panels x 32KB ([256n][64k] 128B rows)
__device__ __align__(16) __half g_B1[65536];              // 128KB
__device__ __align__(16) __half g_B2[65536];

// ---------------- helpers -------------------------------------------------------
__device__ __forceinline__ u32 smem_u32(const void* p) {
    u32 r;
    asm("{ .reg .u64 t; cvta.to.shared.u64 t, %1; cvt.u32.u64 %0, t; }" : "=r"(r) : "l"(p));
    return r;
}
__device__ __forceinline__ void cp16(u32 dst, const void* src) {
    asm volatile("cp.async.cg.shared.global [%0], [%1], 16;" :: "r"(dst), "l"(src) : "memory");
}
__device__ __forceinline__ void cp_commit() { asm volatile("cp.async.commit_group;" ::: "memory"); }
__device__ __forceinline__ void cp_wait0()  { asm volatile("cp.async.wait_group 0;" ::: "memory"); }
__device__ __forceinline__ void cp_wait1()  { asm volatile("cp.async.wait_group 1;" ::: "memory"); }

__device__ __forceinline__ void ldsm4(u32 a, u32 &r0, u32 &r1, u32 &r2, u32 &r3) {
    asm volatile("ldmatrix.sync.aligned.m8n8.x4.shared.b16 {%0,%1,%2,%3}, [%4];"
                 : "=r"(r0), "=r"(r1), "=r"(r2), "=r"(r3) : "r"(a));
}
__device__ __forceinline__ void mma16816(float* c, const u32* a, u32 b0, u32 b1) {
    asm volatile("mma.sync.aligned.m16n8k16.row.col.f32.f16.f16.f32 "
                 "{%0,%1,%2,%3}, {%4,%5,%6,%7}, {%8,%9}, {%0,%1,%2,%3};"
                 : "+f"(c[0]), "+f"(c[1]), "+f"(c[2]), "+f"(c[3])
                 : "r"(a[0]), "r"(a[1]), "r"(a[2]), "r"(a[3]), "r"(b0), "r"(b1));
}

// Order-preserving float <-> uint encoding for atomic min/max
__device__ __forceinline__ unsigned enc_f(float x) {
    unsigned u = __float_as_uint(x);
    return (u & 0x80000000u) ? ~u : (u | 0x80000000u);
}
__device__ __forceinline__ float dec_f(unsigned k) {
    unsigned u = (k & 0x80000000u) ? (k ^ 0x80000000u) : ~k;
    return __uint_as_float(u);
}
__device__ __forceinline__ void min4(float4 &d, float4 v) {
    d.x = fminf(d.x, v.x); d.y = fminf(d.y, v.y);
    d.z = fminf(d.z, v.z); d.w = fminf(d.w, v.w);
}
__device__ __forceinline__ void max4(float4 &d, float4 v) {
    d.x = fmaxf(d.x, v.x); d.y = fmaxf(d.y, v.y);
    d.z = fmaxf(d.z, v.z); d.w = fmaxf(d.w, v.w);
}

// ---------------- kernel 0: init min/max keys -----------------------------------
__global__ void init_keys_kernel() {
    int i = blockIdx.x * blockDim.x + threadIdx.x;
    if (i >= BB * CH_ALL) return;
    int slot = i & (CH_ALL - 1);
    bool is_min = (slot < 128) || (slot >= 256 && slot < 384);
    g_keys[i] = is_min ? 0xFFFFFFFFu : 0x00000000u;
}

// ---------------- kernel 1: transpose img_bev[0] [C][P] -> [P][C] ---------------
__global__ void transpose_kernel(const float* __restrict__ img) {
    __shared__ float tile[32][33];
    int p0 = blockIdx.x * 32;
    int c0 = blockIdx.y * 32;
    int tx = threadIdx.x, ty = threadIdx.y;
#pragma unroll
    for (int j = 0; j < 4; ++j) {
        int c = c0 + ty + j * 8;
        int p = p0 + tx;
        if (p < SPATIAL) tile[ty + j * 8][tx] = img[c * SPATIAL + p];
    }
    __syncthreads();
#pragma unroll
    for (int j = 0; j < 4; ++j) {
        int p = p0 + ty + j * 8;
        int c = c0 + tx;
        if (p < SPATIAL) g_imgT[p * C_C + c] = tile[tx][ty + j * 8];
    }
}

// ---------------- kernel 1b: constant cam min/max for batches 1..3 --------------
// For b>=1: row = b*32400 + y*180 + x >= 32400 is ALWAYS clamped to 32398, so
// every voxel of those batches gathers pixel 32398 -> cmin = cmax = imgT[32398].
__global__ void const_cam_kernel() {
    int i = threadIdx.x;            // 0..383
    int b = 1 + (i >> 7);
    int c = i & 127;
    unsigned e = enc_f(g_imgT[(size_t)(SPATIAL - 2) * C_C + c]);
    atomicMin(&g_keys[b * CH_ALL + 256 + c], e);
    atomicMax(&g_keys[b * CH_ALL + 384 + c], e);
}

// ---------------- kernel 2: per-batch segment min/max ---------------------------
// 128-row chunks (grid 1250 -> better latency hiding); uniform chunks vectorized;
// cam loads skipped entirely for uniform b>=1 chunks (constant).
#define MM_CHUNK 128
__device__ __forceinline__ void flush_mm(int b, int c, float mn, float mx) {
    int msl, xsl;
    if (c < 128) { msl = c;             xsl = 128 + c; }
    else         { msl = 256 + c - 128; xsl = 384 + c - 128; }
    atomicMin(&g_keys[b * CH_ALL + msl], enc_f(mn));
    atomicMax(&g_keys[b * CH_ALL + xsl], enc_f(mx));
}
__global__ void __launch_bounds__(256) minmax_kernel(
    const float* __restrict__ lidar, const int* __restrict__ batch_idx,
    const int* __restrict__ y_idx, const int* __restrict__ x_idx, int N)
{
    __shared__ int sb[MM_CHUNK];
    __shared__ int sr[MM_CHUNK];
    __shared__ float red[4][8][128];
    int tid = threadIdx.x;
    int n0 = blockIdx.x * MM_CHUNK;
    int cnt = N - n0; if (cnt > MM_CHUNK) cnt = MM_CHUNK;
    if (cnt <= 0) return;
    if (tid < cnt) {
        int n = n0 + tid;
        int b = batch_idx[n];
        int r = b * SPATIAL + y_idx[n] * WW + x_idx[n];
        if (r > SPATIAL - 2) r = SPATIAL - 2;
        sb[tid] = b; sr[tid] = r;
    }
    __syncthreads();

    if (cnt == MM_CHUNK && sb[0] == sb[MM_CHUNK - 1]) {
        const int rg = tid >> 5;
        const int c4 = tid & 31;
        const float4* lid4 = (const float4*)lidar;
        const bool do_cam = (sb[0] == 0);   // cam is constant for b>=1
        float4 mnl = make_float4( INFINITY,  INFINITY,  INFINITY,  INFINITY);
        float4 mxl = make_float4(-INFINITY, -INFINITY, -INFINITY, -INFINITY);
        float4 mnc = mnl, mxc = mxl;
        if (do_cam) {
            const float4* img4 = (const float4*)g_imgT;
#pragma unroll 4
            for (int i = 0; i < MM_CHUNK / 8; ++i) {
                int row = i * 8 + rg;
                float4 lv = lid4[(size_t)(n0 + row) * 32 + c4];
                float4 cv = img4[(size_t)sr[row] * 32 + c4];
                min4(mnl, lv); max4(mxl, lv);
                min4(mnc, cv); max4(mxc, cv);
            }
        } else {
#pragma unroll 4
            for (int i = 0; i < MM_CHUNK / 8; ++i) {
                int row = i * 8 + rg;
                float4 lv = lid4[(size_t)(n0 + row) * 32 + c4];
                min4(mnl, lv); max4(mxl, lv);
            }
        }
        int ch = c4 * 4;
        *(float4*)&red[0][rg][ch] = mnl;
        *(float4*)&red[1][rg][ch] = mxl;
        if (do_cam) {
            *(float4*)&red[2][rg][ch] = mnc;
            *(float4*)&red[3][rg][ch] = mxc;
        }
        __syncthreads();
        int c = tid;
        if (c < 128 || do_cam) {
            int qm = (c < 128) ? 0 : 2;
            int cc = c & 127;
            float mn = red[qm][0][cc], mx = red[qm + 1][0][cc];
#pragma unroll
            for (int g = 1; g < 8; ++g) {
                mn = fminf(mn, red[qm][g][cc]);
                mx = fmaxf(mx, red[qm + 1][g][cc]);
            }
            flush_mm(sb[0], c, mn, mx);
        }
    } else {
        const int c = tid & 255;
        if (tid < 256) {
            const bool cam = (c >= 128);
            const float* base = cam ? (g_imgT + (c - 128)) : (lidar + c);
            float mn = INFINITY, mx = -INFINITY;
            int cur = sb[0];
            for (int i = 0; i < cnt; ++i) {
                int b = sb[i];
                if (b != cur) { flush_mm(cur, c, mn, mx); cur = b; mn = INFINITY; mx = -INFINITY; }
                float v = cam ? base[(size_t)sr[i] * C_C] : base[(size_t)(n0 + i) * C_L];
                mn = fminf(mn, v); mx = fmaxf(mx, v);
            }
            flush_mm(cur, c, mn, mx);
        }
    }
}

// ---------------- kernel 3a/3b: tiny gating MLPs --------------------------------
__global__ void __launch_bounds__(256) mlp1_kernel(
    const float* __restrict__ Wl1, const float* __restrict__ Wc1)
{
    int gw   = blockIdx.x * 8 + (threadIdx.x >> 5);
    int lane = threadIdx.x & 31;
    int net  = gw / (BB * CH_HID);
    int rem  = gw % (BB * CH_HID);
    int b    = rem / CH_HID;
    int j    = rem % CH_HID;
    const float* W = net ? Wc1 : Wl1;
    float s = 0.f;
#pragma unroll
    for (int t = 0; t < 16; ++t) {
        int k = lane + 32 * t;
        s = fmaf(dec_f(g_keys[b * CH_ALL + k]), W[k * CH_HID + j], s);
    }
#pragma unroll
    for (int o = 16; o; o >>= 1) s += __shfl_xor_sync(0xffffffffu, s, o);
    if (lane == 0) g_hid[net][b][j] = fmaxf(s, 0.f);
}
__global__ void __launch_bounds__(256) mlp2_kernel(
    const float* __restrict__ Wl2, const float* __restrict__ Wc2)
{
    int idx = blockIdx.x * 256 + threadIdx.x;
    int net = idx >> 9, rem = idx & 511;
    int b = rem >> 7, cc = rem & 127;
    const float* W2 = net ? Wc2 : Wl2;
    const float* h  = g_hid[net][b];
    float s = 0.f;
    for (int k = 0; k < CH_HID; ++k) s = fmaf(h[k], W2[k * 128 + cc], s);
    float v = fmaxf(s, 0.f);
    (net ? g_att_c : g_att_l)[b * 128 + cc] = 1.f / (1.f + expf(-v));
}

// ---------------- kernel 3d: per-batch GEMM1 cam bias (fp32) --------------------
// hc[b][n] = sum_k (att_c[b][k] * imgT[32398][k]) * Wf1[128+k][n]
__global__ void __launch_bounds__(256) hc_kernel(const float* __restrict__ Wf1) {
    __shared__ float gc[128];
    int b = blockIdx.x, t = threadIdx.x;
    if (t < 128) gc[t] = g_att_c[b * 128 + t] * g_imgT[(size_t)(SPATIAL - 2) * C_C + t];
    __syncthreads();
    float s = 0.f;
#pragma unroll 4
    for (int k = 0; k < 128; ++k)
        s = fmaf(gc[k], Wf1[(128 + k) * 256 + t], s);
    g_hc[b * 256 + t] = s;
}

// ---------------- kernel 3c: weight prep (transpose + fp16 + pre-swizzle) -------
__global__ void __launch_bounds__(256) weight_prep_kernel(
    const float* __restrict__ Wf1, const float* __restrict__ Wf2)
{
    int idx = blockIdx.x * 256 + threadIdx.x;   // 2 * 65536
    int mat = idx >> 16;
    int rem = idx & 65535;
    int k = rem >> 8;          // 0..255 input dim
    int n = rem & 255;         // 0..255 output dim
    const float* W = mat ? Wf2 : Wf1;
    __half hv = __float2half_rn(W[k * 256 + n]);
    int p = k >> 6, k8l = (k >> 3) & 7, e = k & 7;
    u32 off = (u32)p * 32768u + (u32)n * 128u + ((u32)(k8l ^ (n & 7)) << 4) + (u32)e * 2u;
    __half* img = mat ? g_B2 : g_B1;
    *(unsigned short*)((char*)img + off) = *(unsigned short*)&hv;
}

// ---------------- B panel-0 prefetch (buf0) ---------------------------------------
__device__ __forceinline__ void preload_B0(u32 smb, const uint4* __restrict__ Bimg, int tid) {
    u32 dst = smb + SM_B + (u32)tid * 16u;
    const uint4* s = Bimg + tid;
#pragma unroll
    for (int i = 0; i < 8; ++i) cp16(dst + i * 4096u, s + i * 256);
    cp_commit();
}

// ---------------- fused GEMM stage (M=64, fp16 single-term, NP panels) -----------
// Panel 0 must already be prefetched into buf0 (one pending commit group).
template<int NP>
__device__ __forceinline__ void gemm_stage(
    u32 smb, u32 Abase, const uint4* __restrict__ Bimg,
    float acc[2][8][4], int tid, int lane, int wm, int wn)
{
    const u32 Bb = smb + SM_B;
#pragma unroll 1
    for (int p = 0; p < NP; ++p) {
        if (p < NP - 1) {
            u32 dst = Bb + (u32)((p + 1) & 1) * 32768u + (u32)tid * 16u;
            const uint4* s = Bimg + (p + 1) * 2048 + tid;
#pragma unroll
            for (int i = 0; i < 8; ++i) cp16(dst + i * 4096u, s + i * 256);
            cp_commit();
            cp_wait1();
        } else {
            cp_wait0();
        }
        __syncthreads();
        u32 B = Bb + (u32)(p & 1) * 32768u;
#pragma unroll
        for (int s = 0; s < 4; ++s) {
            int k8 = p * 8 + s * 2 + (lane >> 4);    // A unit index
            int arow = wm + (lane & 15);
            u32 aoff = (u32)arow * 512u + ((u32)(k8 ^ (arow & 7)) << 4);
            u32 ah[2][4];
            ldsm4(Abase + aoff,          ah[0][0], ah[0][1], ah[0][2], ah[0][3]);
            ldsm4(Abase + aoff + 8192u,  ah[1][0], ah[1][1], ah[1][2], ah[1][3]);
            int k8h = s * 2 + (lane >> 4);
            u32 bh[8][2];
#pragma unroll
            for (int j16 = 0; j16 < 4; ++j16) {
                int brow = wn + j16 * 16 + (lane & 15);
                u32 rb = B + (u32)brow * 128u;
                u32 r0, r1, r2, r3;
                ldsm4(rb + ((u32)(k8h ^ (brow & 7)) << 4), r0, r1, r2, r3);
                bh[2*j16][0] = r0;   bh[2*j16][1] = r2;
                bh[2*j16+1][0] = r1; bh[2*j16+1][1] = r3;
            }
#pragma unroll
            for (int t = 0; t < 2; ++t)
#pragma unroll
                for (int j = 0; j < 8; ++j)
                    mma16816(acc[t][j], ah[t], bh[j][0], bh[j][1]);
        }
        __syncthreads();
    }
}

// ---------------- kernel 4: fused gate + GEMM1 + ReLU + GEMM2 + ReLU -------------
__global__ void __launch_bounds__(256, 2) fused_mma_kernel(
    const float* __restrict__ lidar,
    const int* __restrict__ batch_idx,
    const int* __restrict__ y_idx,
    const int* __restrict__ x_idx,
    float* __restrict__ out, int N)
{
    extern __shared__ char sm[];
    const u32 smb = smem_u32(sm);
    int* sbv = (int*)(sm + SM_SB);
    const int tid  = threadIdx.x;
    const int lane = tid & 31;
    const int wid  = tid >> 5;
    const int wm   = (wid & 1) * 32;
    const int wn   = (wid >> 1) * 64;

    // tile is "short" (cam half constant -> K=128 GEMM1 + bias) iff first row b>=1
    int first_n = blockIdx.x * 64;
    if (first_n >= N) first_n = N - 1;
    const bool short_tile = (batch_idx[first_n] >= 1);

    // prefetch GEMM1 B panel 0 NOW — overlaps the phase-1 gather below
    preload_B0(smb, (const uint4*)g_B1, tid);

    // ---- phase 1: gather + gate + fp16 cvt into A smem (swizzled) ----
    {
        int m = tid >> 2, q = tid & 3;          // 4 threads per row, 64 ch each
        int n = blockIdx.x * 64 + m;
        int nn = n < N ? n : N - 1;
        int b = batch_idx[nn];
        if (q == 0) sbv[m] = b;
        if (!(short_tile && q >= 2)) {          // skip cam gather on short tiles
            const float* src;
            const float* att;
            if (q < 2) { src = lidar + (size_t)nn * C_L; att = g_att_l + b * 128; }
            else {
                int r = b * SPATIAL + y_idx[nn] * WW + x_idx[nn];
                if (r > SPATIAL - 2) r = SPATIAL - 2;
                src = g_imgT + (size_t)r * C_C; att = g_att_c + b * 128;
            }
            const float4* s4 = (const float4*)src;
            const float4* g4 = (const float4*)att;
            int ho = (q & 1) * 16;
            u32 rowb = (u32)m * 512u;
            u32 xm = (u32)(m & 7);
#pragma unroll
            for (int i = 0; i < 8; ++i) {
                float4 a0 = s4[ho + 2*i], a1 = s4[ho + 2*i + 1];
                float4 q0 = g4[ho + 2*i], q1 = g4[ho + 2*i + 1];
                __half2 h0 = __floats2half2_rn(a0.x*q0.x, a0.y*q0.y);
                __half2 h1 = __floats2half2_rn(a0.z*q0.z, a0.w*q0.w);
                __half2 h2 = __floats2half2_rn(a1.x*q1.x, a1.y*q1.y);
                __half2 h3 = __floats2half2_rn(a1.z*q1.z, a1.w*q1.w);
                uint4 H = make_uint4(*(u32*)&h0, *(u32*)&h1, *(u32*)&h2, *(u32*)&h3);
                u32 k8 = (u32)(q * 8 + i);
                u32 off = rowb + ((k8 ^ xm) << 4);
                *(uint4*)(sm + SM_AH + off) = H;
            }
        }
    }
    __syncthreads();   // sbv + A visible

    // ---- acc init: zero (full) or per-row cam bias hc[b] (short) ----
    float acc[2][8][4];
    if (short_tile) {
#pragma unroll
        for (int t = 0; t < 2; ++t) {
            int r0 = wm + 16 * t + (lane >> 2);
            int r1 = r0 + 8;
            const float* h0 = g_hc + sbv[r0] * 256;
            const float* h1 = g_hc + sbv[r1] * 256;
#pragma unroll
            for (int j = 0; j < 8; ++j) {
                int col = wn + 8 * j + 2 * (lane & 3);
                acc[t][j][0] = h0[col];   acc[t][j][1] = h0[col + 1];
                acc[t][j][2] = h1[col];   acc[t][j][3] = h1[col + 1];
            }
        }
    } else {
#pragma unroll
        for (int t = 0; t < 2; ++t)
#pragma unroll
            for (int j = 0; j < 8; ++j)
#pragma unroll
                for (int c = 0; c < 4; ++c) acc[t][j][c] = 0.f;
    }

    // ---- GEMM1: K=128 (short) or K=256 (full) ----
    if (short_tile)
        gemm_stage<2>(smb, smb + SM_AH, (const uint4*)g_B1, acc, tid, lane, wm, wn);
    else
        gemm_stage<4>(smb, smb + SM_AH, (const uint4*)g_B1, acc, tid, lane, wm, wn);

    // prefetch GEMM2 B panel 0 — overlaps epilogue 1 (buf0 is free: GEMM1's
    // trailing __syncthreads means no warp still reads B)
    preload_B0(smb, (const uint4*)g_B2, tid);

    // ---- epilogue 1: relu + fp16 cvt -> h (overwrites A smem; GEMM1's trailing
    //      __syncthreads guarantees all A reads are complete) ----
    {
#pragma unroll
        for (int t = 0; t < 2; ++t) {
            int r0 = wm + 16 * t + (lane >> 2);
            int r1 = r0 + 8;
#pragma unroll
            for (int j = 0; j < 8; ++j) {
                float* c = acc[t][j];
                u32 k8 = (u32)((wn >> 3) + j);
                u32 eb = (u32)(lane & 3) * 4u;
                __half2 p0 = __floats2half2_rn(fmaxf(c[0], 0.f), fmaxf(c[1], 0.f));
                __half2 p1 = __floats2half2_rn(fmaxf(c[2], 0.f), fmaxf(c[3], 0.f));
                u32 o0 = (u32)r0 * 512u + ((k8 ^ (u32)(r0 & 7)) << 4) + eb;
                u32 o1 = (u32)r1 * 512u + ((k8 ^ (u32)(r1 & 7)) << 4) + eb;
                *(u32*)(sm + SM_AH + o0) = *(u32*)&p0;
                *(u32*)(sm + SM_AH + o1) = *(u32*)&p1;
            }
        }
    }
    __syncthreads();

#pragma unroll
    for (int t = 0; t < 2; ++t)
#pragma unroll
        for (int j = 0; j < 8; ++j)
#pragma unroll
            for (int c = 0; c < 4; ++c) acc[t][j][c] = 0.f;

    // ---- GEMM2 ----
    gemm_stage<4>(smb, smb + SM_AH, (const uint4*)g_B2, acc, tid, lane, wm, wn);

    // ---- epilogue 2: relu -> gmem ----
    {
        int mbase = blockIdx.x * 64;
#pragma unroll
        for (int t = 0; t < 2; ++t) {
            int r0 = mbase + wm + 16 * t + (lane >> 2);
            int r1 = r0 + 8;
#pragma unroll
            for (int j = 0; j < 8; ++j) {
                float* c = acc[t][j];
                int col = wn + 8 * j + 2 * (lane & 3);
                if (r0 < N) {
                    float2 v = make_float2(fmaxf(c[0], 0.f), fmaxf(c[1], 0.f));
                    *(float2*)(out + (size_t)r0 * 256 + col) = v;
                }
                if (r1 < N) {
                    float2 v = make_float2(fmaxf(c[2], 0.f), fmaxf(c[3], 0.f));
                    *(float2*)(out + (size_t)r1 * 256 + col) = v;
                }
            }
        }
    }
}

// ---------------- host launcher ---------------------------------------------------
extern "C" void kernel_launch(void* const* d_in, const int* in_sizes, int n_in,
                              void* d_out, int out_size)
{
    int iL = -1, iImg = -1, iB = -1, iY = -1, iX = -1;
    int iWl1 = -1, iWl2 = -1, iWc1 = -1, iWc2 = -1, iWf1 = -1, iWf2 = -1;
    for (int i = 0; i < n_in; ++i) {
        int s = in_sizes[i];
        if      (s == BB * C_C * SPATIAL)      iImg = i;
        else if (s == CH_ALL * CH_HID)         { if (iWl1 < 0) iWl1 = i; else iWc1 = i; }
        else if (s == CH_HID * C_L)            { if (iWl2 < 0) iWl2 = i; else iWc2 = i; }
        else if (s == C_OUT * C_OUT)           { if (iWf1 < 0) iWf1 = i; else iWf2 = i; }
        else if (s % C_L == 0 && s >= 1000000) iL = i;
        else                                   { if (iB < 0) iB = i; else if (iY < 0) iY = i; else iX = i; }
    }
    const float* lidar = (const float*)d_in[iL];
    const float* img   = (const float*)d_in[iImg];
    const int*   bidx  = (const int*)d_in[iB];
    const int*   yidx  = (const int*)d_in[iY];
    const int*   xidx  = (const int*)d_in[iX];
    const float* Wl1   = (const float*)d_in[iWl1];
    const float* Wl2   = (const float*)d_in[iWl2];
    const float* Wc1   = (const float*)d_in[iWc1];
    const float* Wc2   = (const float*)d_in[iWc2];
    const float* Wf1   = (const float*)d_in[iWf1];
    const float* Wf2   = (const float*)d_in[iWf2];
    float* out = (float*)d_out;
    const int N = in_sizes[iL] / C_L;

    cudaFuncSetAttribute(fused_mma_kernel, cudaFuncAttributeMaxDynamicSharedMemorySize, SMEM_TOTAL);

    init_keys_kernel<<<(BB * CH_ALL + 255) / 256, 256>>>();
    transpose_kernel<<<dim3((SPATIAL + 31) / 32, C_C / 32), dim3(32, 8)>>>(img);
    const_cam_kernel<<<1, 384>>>();
    weight_prep_kernel<<<512, 256>>>(Wf1, Wf2);
    minmax_kernel<<<(N + MM_CHUNK - 1) / MM_CHUNK, 256>>>(lidar, bidx, yidx, xidx, N);
    mlp1_kernel<<<CH_HID, 256>>>(Wl1, Wc1);
    mlp2_kernel<<<4, 256>>>(Wl2, Wc2);
    hc_kernel<<<BB, 256>>>(Wf1);
    fused_mma_kernel<<<(N + 63) / 64, 256, SMEM_TOTAL>>>(lidar, bidx, yidx, xidx, out, N);
    (void)out_size;
}